// round 13
// baseline (speedup 1.0000x reference)
#include <cuda_runtime.h>
#include <cuda_fp16.h>
#include <cuda_bf16.h>
#include <cstdint>

#define B_   64
#define N_   1024
#define BN   65536
#define H_   128
#define S_   12
#define CSR_CAP 512

#define NGATE   512
#define K0_LDA  448      // layer0 cols: x0[h|x|pad]@0..131, x1@132, x2@264, tail 396..447 zero
#define K1_LDA  768      // layer1 cols: x0@0(256: h_new|h1) x1@256 x2@512
#define NKT0    28       // B-frag layout stride for layer0
#define NKT0_LOOP 25     // cols 400..447 are all-zero -> skip 3 K-tiles
#define NKT1    48

// d_out layout: [output 65536][hs 2*BN*H][cs 2*BN*H][attw BN*S]
#define HS_OFF   65536
#define CS_OFF   (65536 + 2 * BN * H_)
#define ATT_OFF  (CS_OFF + 2 * BN * H_)

// ---------------- scratch (device globals; zero-initialized) ---------------
__device__ float g_feats [(size_t)BN * K0_LDA];
__device__ float g_feats2[(size_t)BN * K1_LDA];
__device__ float g_energy[S_ * BN];
__device__ float g_dpw[S_ * BN];
__device__ int   g_csr_cnt[N_];
__device__ int   g_csr_col[(size_t)N_ * CSR_CAP];
__device__ float g_csr_val[(size_t)N_ * CSR_CAP];
// fp16 single-plane weights, mma-fragment-linear
__device__ __half g_wt0[(size_t)512 * K0_LDA];
__device__ __half g_wt1[(size_t)512 * K1_LDA];
__device__ __half g_aw [(size_t)128 * 128];    // attn_w^T [n][k], fp16

__device__ __forceinline__ float sigmoidf_(float x) { return 1.f / (1.f + expf(-x)); }

__device__ __forceinline__ uint32_t smem_u32(const void* p) {
    uint32_t a;
    asm("{ .reg .u64 t; cvta.to.shared.u64 t, %1; cvt.u32.u64 %0, t; }"
        : "=r"(a) : "l"(p));
    return a;
}
__device__ __forceinline__ void ldsm_x4(uint32_t* r, uint32_t addr) {
    asm volatile("ldmatrix.sync.aligned.m8n8.x4.shared.b16 {%0,%1,%2,%3}, [%4];"
                 : "=r"(r[0]), "=r"(r[1]), "=r"(r[2]), "=r"(r[3]) : "r"(addr));
}
__device__ __forceinline__ void mma_f16(float* d, const uint32_t* a,
                                        const uint32_t* b) {
    asm volatile(
        "mma.sync.aligned.m16n8k16.row.col.f32.f16.f16.f32 "
        "{%0,%1,%2,%3}, {%4,%5,%6,%7}, {%8,%9}, {%0,%1,%2,%3};"
        : "+f"(d[0]), "+f"(d[1]), "+f"(d[2]), "+f"(d[3])
        : "r"(a[0]), "r"(a[1]), "r"(a[2]), "r"(a[3]), "r"(b[0]), "r"(b[1]));
}

// ---- B-fragment addressing: tile(nt2 16-cols, kt) ; regs b0e,b1e,b0o,b1o --
__device__ __forceinline__ size_t bfrag_idx(int k, int n, int nkt) {
    int nt2 = n >> 4, half = (n >> 3) & 1, kt = k >> 4, kk = k & 15;
    return ((size_t)nt2 * nkt + kt) * 256
         + (size_t)(((n & 7) << 2) | ((kk >> 1) & 3)) * 8
         + (size_t)((half << 1) | (kk >> 3)) * 2 + (kk & 1);
}

// ---------------- fused setup: csr + fills + weight splits -----------------
// block ranges: [0,128) csr | [128,8576) fill_x0_l0 | [8576,9472) wsplit0
// [9472,11008) wsplit1 | [11008,11072) awsplit | [11072,19264) fill_h1
__global__ __launch_bounds__(256) void setup_kernel(
    const float* __restrict__ inputs, const float* __restrict__ h0,
    const float* __restrict__ h1, const float* __restrict__ sup,
    const float* __restrict__ w0, const float* __restrict__ w1,
    const float* __restrict__ aw) {
    int blk = blockIdx.x;
    int tid = threadIdx.x;
    if (blk < 128) {
        int n = blk * 8 + (tid >> 5);
        int lane = tid & 31;
        const float* row = sup + (size_t)n * N_;
        int cnt = 0;
        for (int base = 0; base < N_; base += 32) {
            float v = row[base + lane];
            unsigned mask = __ballot_sync(0xffffffffu, v != 0.f);
            if (v != 0.f) {
                int pos = cnt + __popc(mask & ((1u << lane) - 1u));
                if (pos < CSR_CAP) {
                    g_csr_col[n * CSR_CAP + pos] = base + lane;
                    g_csr_val[n * CSR_CAP + pos] = v;
                }
            }
            cnt += __popc(mask);
        }
        if (lane == 0) g_csr_cnt[n] = cnt < CSR_CAP ? cnt : CSR_CAP;
    } else if (blk < 8576) {
        int t = (blk - 128) * 256 + tid;
        if (t >= BN * 33) return;
        int r = t / 33, u = t - r * 33;
        float* dst = g_feats + (size_t)r * K0_LDA;
        if (u < 32) {
            ((float4*)dst)[u] = ((const float4*)(h0 + (size_t)r * H_))[u];
        } else {
            dst[128] = inputs[r];
            dst[129] = 0.f; dst[130] = 0.f; dst[131] = 0.f;
        }
    } else if (blk < 9472) {
        int t = (blk - 8576) * 256 + tid;
        if (t >= 512 * K0_LDA) return;
        int n_il = t / K0_LDA, k = t - n_il * K0_LDA;
        int n = (n_il & 3) * 128 + (n_il >> 2);
        int r = -1;
        if (k < 396) {
            int seg = (k * 0x3E1) >> 17;          // k/132 for k<396
            int p = k - seg * 132;
            int f = (p < 128) ? p + 1 : (p == 128 ? 0 : -1);
            if (f >= 0) r = seg * 129 + f;
        }
        float v = (r >= 0) ? w0[(size_t)r * NGATE + n] : 0.f;
        g_wt0[bfrag_idx(k, n_il, NKT0)] = __float2half_rn(v);
    } else if (blk < 11008) {
        int t = (blk - 9472) * 256 + tid;
        if (t >= 512 * K1_LDA) return;
        int n_il = t / K1_LDA, k = t - n_il * K1_LDA;
        int n = (n_il & 3) * 128 + (n_il >> 2);
        float v = w1[(size_t)k * NGATE + n];
        g_wt1[bfrag_idx(k, n_il, NKT1)] = __float2half_rn(v);
    } else if (blk < 11072) {
        int t = (blk - 11008) * 256 + tid;
        int n = t >> 7, k = t & 127;
        g_aw[t] = __float2half_rn(aw[k * 128 + n]);
    } else {
        int t = (blk - 11072) * 256 + tid;
        if (t >= BN * 32) return;
        int r = t >> 5, u = t & 31;
        ((float4*)(g_feats2 + (size_t)r * K1_LDA + 128))[u] =
            ((const float4*)(h1 + (size_t)r * H_))[u];
    }
}

// ---------------- vectorized sparse diffusion (fp32 only) ------------------
__global__ __launch_bounds__(128) void spmmv_kernel(int buf, int ld, int srcCol,
                                                    int dstCol, int prevCol,
                                                    int D4, int cheb) {
    __shared__ int   scol[CSR_CAP];   // pre-multiplied by ld
    __shared__ float sval[CSR_CAP];
    float* F = buf ? g_feats2 : g_feats;
    int n = blockIdx.x;
    int tid = threadIdx.x, bq = tid >> 5, tq = tid & 31;
    int cnt = g_csr_cnt[n];
    for (int i = tid; i < cnt; i += 128) {
        scol[i] = g_csr_col[n * CSR_CAP + i] * ld;
        sval[i] = g_csr_val[n * CSR_CAP + i];
    }
    __syncthreads();
    int b = blockIdx.y * 4 + bq;
    const float* srcB = F + (size_t)b * N_ * ld + srcCol;
    size_t rbase = ((size_t)b * N_ + n) * ld;
    for (int d0 = tq * 4; d0 < D4; d0 += 128) {
        float4 acc = make_float4(0.f, 0.f, 0.f, 0.f);
        for (int i = 0; i < cnt; i++) {
            const float4 v = *(const float4*)(srcB + scol[i] + d0);
            float s = sval[i];
            acc.x += s * v.x; acc.y += s * v.y; acc.z += s * v.z; acc.w += s * v.w;
        }
        if (cheb) {
            float4 p = *(const float4*)(F + rbase + prevCol + d0);
            acc.x = 2.f * acc.x - p.x; acc.y = 2.f * acc.y - p.y;
            acc.z = 2.f * acc.z - p.z; acc.w = 2.f * acc.w - p.w;
        }
        *(float4*)(F + rbase + dstCol + d0) = acc;
    }
}

// ---------------- gates GEMM + fused LSTM: fp16 2-product, smem-A ----------
// Block 64x128, 8 warps (2x4), warp tile 32x32, 2 CTA/SM.
// A: coalesced float4/thread -> padded smem (stride 24 fl, conflict-free LDS.64)
// B: single fp16 fragment-linear plane, reg double-buffered.
#define A_SROW 24
#define A_BUFSZ (64 * A_SROW)
__global__ __launch_bounds__(256, 2) void gates_mma_kernel(
    const float* __restrict__ bias, const float* __restrict__ c_in,
    float* __restrict__ h_out, float* __restrict__ c_out,
    int lda, int nktLayout, int nktLoop, int layer) {
    __shared__ float sA[2 * A_BUFSZ];

    const float* F = layer ? g_feats2 : g_feats;
    const uint4* BW = layer ? (const uint4*)g_wt1 : (const uint4*)g_wt0;

    int tid = threadIdx.x, lane = tid & 31, wid = tid >> 5;
    int warpM = wid & 1, warpN = wid >> 1;       // 2 x 4
    int colBase = blockIdx.x * 128;              // col fastest: A reuse in L2
    size_t rowBase = (size_t)blockIdx.y * 64;

    // A gmem loader: thread t -> row t>>2, col-group (t&3)*4 (one float4)
    int ldRow = tid >> 2, ldCol = (tid & 3) * 4;
    const float* aGm = F + (rowBase + ldRow) * (size_t)lda + ldCol;
    float* aSt = &sA[ldRow * A_SROW + ldCol];

    // fragment LDS bases: rows warpM*32 + (lane>>2) + j*8, col (lane&3)*2
    const float* aLd[4];
#pragma unroll
    for (int j = 0; j < 4; j++)
        aLd[j] = &sA[(warpM * 32 + (lane >> 2) + j * 8) * A_SROW + (lane & 3) * 2];

    size_t tstride = (size_t)nktLayout * 32;
    size_t bOff0 = ((size_t)(colBase >> 4) + (size_t)warpN * 2) * tstride + lane;
    size_t bOff1 = bOff0 + tstride;

    float acc[2][2][2][4];
#pragma unroll
    for (int i = 0; i < 2; i++)
#pragma unroll
        for (int j = 0; j < 2; j++)
#pragma unroll
            for (int k = 0; k < 2; k++)
#pragma unroll
                for (int q = 0; q < 4; q++) acc[i][j][k][q] = 0.f;

    uint4 vB[2][2];                // [buf][nt2]

    // prologue: stage A tile 0, prefetch A tile 1 (gmem), B tile 0 (regs)
    float4 pv = *(const float4*)aGm;
    *(float4*)aSt = pv;
    if (nktLoop > 1) pv = *(const float4*)(aGm + 16);
    vB[0][0] = BW[bOff0];
    vB[0][1] = BW[bOff1];
    __syncthreads();

    for (int kt = 0; kt < nktLoop; kt++) {
        int cur = kt & 1;
        // prefetch next B into the other reg buffer
        if (kt + 1 < nktLoop) {
            size_t ko = (size_t)(kt + 1) * 32;
            vB[cur ^ 1][0] = BW[bOff0 + ko];
            vB[cur ^ 1][1] = BW[bOff1 + ko];
        }
        // read A fragments from smem (conflict-free LDS.64)
        float2 f[4][2];
#pragma unroll
        for (int j = 0; j < 4; j++) {
            f[j][0] = *(const float2*)(aLd[j] + cur * A_BUFSZ);
            f[j][1] = *(const float2*)(aLd[j] + cur * A_BUFSZ + 8);
        }
        // stage A tile kt+1 into the other smem buffer; prefetch kt+2 gmem
        if (kt + 1 < nktLoop) {
            *(float4*)(aSt + (cur ^ 1) * A_BUFSZ) = pv;
            if (kt + 2 < nktLoop) pv = *(const float4*)(aGm + (kt + 2) * 16);
        }
        // convert fp32 -> fp16 hi/lo fragments
        uint32_t aH[2][4], aL[2][4];
#pragma unroll
        for (int rt = 0; rt < 2; rt++)
#pragma unroll
            for (int pos = 0; pos < 2; pos++)
#pragma unroll
                for (int rj = 0; rj < 2; rj++) {
                    float2 v = f[rt * 2 + rj][pos];
                    __half2 h2 = __floats2half2_rn(v.x, v.y);
                    float2 hb = __half22float2(h2);
                    __half2 l2 = __floats2half2_rn(v.x - hb.x, v.y - hb.y);
                    aH[rt][pos * 2 + rj] = *(uint32_t*)&h2;
                    aL[rt][pos * 2 + rj] = *(uint32_t*)&l2;
                }
#pragma unroll
        for (int rt = 0; rt < 2; rt++)
#pragma unroll
            for (int nt = 0; nt < 2; nt++) {
                const uint32_t* b = (const uint32_t*)&vB[cur][nt];
                mma_f16(acc[rt][nt][0], aH[rt], b);
                mma_f16(acc[rt][nt][0], aL[rt], b);
                mma_f16(acc[rt][nt][1], aH[rt], b + 2);
                mma_f16(acc[rt][nt][1], aL[rt], b + 2);
            }
        __syncthreads();
    }

    // ---- fused LSTM epilogue (col c = 4h+g; lane-pair shuffle) ----
    int evenp = (lane & 1) == 0;
#pragma unroll
    for (int rt = 0; rt < 2; rt++) {
#pragma unroll
        for (int rp = 0; rp < 2; rp++) {
            size_t row = rowBase + warpM * 32 + rt * 16 + rp * 8 + (lane >> 2);
#pragma unroll
            for (int nt = 0; nt < 2; nt++) {
#pragma unroll
                for (int hf = 0; hf < 2; hf++) {
                    int cbase = colBase + warpN * 32 + nt * 16 + hf * 8 + (lane & 3) * 2;
                    int h = cbase >> 2;
                    float a0 = acc[rt][nt][hf][rp * 2 + 0];
                    float a1 = acc[rt][nt][hf][rp * 2 + 1];
                    float v0, v1;
                    if (evenp) {
                        v0 = sigmoidf_(a0 + __ldg(bias + h));          // i
                        v1 = sigmoidf_(a1 + __ldg(bias + 128 + h));    // f
                    } else {
                        v0 = sigmoidf_(a0 + __ldg(bias + 256 + h));    // o
                        v1 = tanhf(a1 + __ldg(bias + 384 + h));        // g
                    }
                    float ex = __shfl_xor_sync(0xffffffffu, v1, 1);
                    float tn = 0.f;
                    if (evenp) {
                        float cin = c_in[row * H_ + h];
                        float cn = v1 * cin + v0 * ex;                 // f*c + i*g
                        c_out[row * H_ + h] = cn;
                        tn = tanhf(cn);
                    }
                    float t2 = __shfl_xor_sync(0xffffffffu, tn, 1);
                    if (!evenp) {
                        float hv = v0 * t2;                            // o*tanh(cn)
                        h_out[row * H_ + h] = hv;
                        if (layer == 0)
                            g_feats2[row * (size_t)K1_LDA + h] = hv;
                    }
                }
            }
        }
    }
}

// ---------------- mma attention energy + dpw (fp16 2-product, smem) --------
#define SROW 12
#define STAGE_U32 (128 * SROW)
__global__ __launch_bounds__(256) void energy_mma_kernel(
    const float* __restrict__ enc, const float* __restrict__ attn_b,
    const float* __restrict__ proj_w, const float* __restrict__ hout) {
    __shared__ __align__(16) uint32_t sAh[2][STAGE_U32];
    __shared__ __align__(16) uint32_t sAl[2][STAGE_U32];
    __shared__ __align__(16) uint32_t sB [2][STAGE_U32];

    int tid = threadIdx.x, lane = tid & 31, wid = tid >> 5;
    int warpM = wid & 3, warpN = wid >> 2;
    size_t tileBase = (size_t)blockIdx.x * 128;

    uint32_t aAH[2], aAL[2], bAd[4];
#pragma unroll
    for (int am = 0; am < 2; am++) {
        int r = warpM * 32 + am * 16 + (lane & 15);
        int c = (lane >> 4) * 4;
        aAH[am] = smem_u32(&sAh[0][r * SROW + c]);
        aAL[am] = smem_u32(&sAl[0][r * SROW + c]);
    }
#pragma unroll
    for (int p = 0; p < 4; p++) {
        int quad = lane >> 3;
        int rowo = ((quad == 0 || quad == 1) ? 0 : 8) + (lane & 7);
        int c = (quad & 1) * 4;
        int n = warpN * 64 + p * 16 + rowo;
        bAd[p] = smem_u32(&sB[0][n * SROW + c]);
    }

    float acc[2][8][4];
#pragma unroll
    for (int i = 0; i < 2; i++)
#pragma unroll
        for (int j = 0; j < 8; j++)
#pragma unroll
            for (int q = 0; q < 4; q++) acc[i][j][q] = 0.f;

    int lr = tid >> 1;
    int lh = (tid & 1) * 8;
    const float* aSrc = enc + (tileBase + lr) * (size_t)H_ + lh;
    const uint4* bSrc = (const uint4*)(g_aw + (size_t)lr * 128 + lh);
    int dstIdx = lr * SROW + (lh >> 1);

    float dpw = 0.f;

    float4 pv0 = ((const float4*)aSrc)[0];
    float4 pv1 = ((const float4*)aSrc)[1];
    uint4 pb = bSrc[0];

    const int nch = H_ / 16;  // 8
    for (int kc = 0; kc < nch; kc++) {
        int st = kc & 1;
        {
            float vv[8] = {pv0.x, pv0.y, pv0.z, pv0.w, pv1.x, pv1.y, pv1.z, pv1.w};
            const float4* pwp = (const float4*)(proj_w + 128 + kc * 16 + lh);
            float4 w0 = __ldg(pwp), w1 = __ldg(pwp + 1);
            dpw += vv[0] * w0.x + vv[1] * w0.y + vv[2] * w0.z + vv[3] * w0.w
                 + vv[4] * w1.x + vv[5] * w1.y + vv[6] * w1.z + vv[7] * w1.w;
            uint32_t hh[4], ll[4];
#pragma unroll
            for (int i = 0; i < 4; i++) {
                float x = vv[2 * i], y = vv[2 * i + 1];
                __half2 hp = __floats2half2_rn(x, y);
                float2 hb = __half22float2(hp);
                __half2 lp = __floats2half2_rn(x - hb.x, y - hb.y);
                hh[i] = *(uint32_t*)&hp;
                ll[i] = *(uint32_t*)&lp;
            }
            *(uint4*)&sAh[st][dstIdx] = make_uint4(hh[0], hh[1], hh[2], hh[3]);
            *(uint4*)&sAl[st][dstIdx] = make_uint4(ll[0], ll[1], ll[2], ll[3]);
            *(uint4*)&sB [st][dstIdx] = pb;
        }
        __syncthreads();
        if (kc + 1 < nch) {
            const float4* s = (const float4*)(aSrc + (kc + 1) * 16);
            pv0 = s[0]; pv1 = s[1];
            pb = bSrc[(kc + 1) * 2];
        }
        uint32_t soff = st * (STAGE_U32 * 4);

        uint32_t aH[2][4], aL[2][4], bv[4][4];
#pragma unroll
        for (int am = 0; am < 2; am++) {
            ldsm_x4(aH[am], aAH[am] + soff);
            ldsm_x4(aL[am], aAL[am] + soff);
        }
#pragma unroll
        for (int p = 0; p < 4; p++)
            ldsm_x4(bv[p], bAd[p] + soff);

#pragma unroll
        for (int am = 0; am < 2; am++) {
#pragma unroll
            for (int p = 0; p < 4; p++) {
                mma_f16(acc[am][2 * p],     aH[am], &bv[p][0]);
                mma_f16(acc[am][2 * p],     aL[am], &bv[p][0]);
                mma_f16(acc[am][2 * p + 1], aH[am], &bv[p][2]);
                mma_f16(acc[am][2 * p + 1], aL[am], &bv[p][2]);
            }
        }
    }

    {
        float d2 = dpw + __shfl_xor_sync(0xffffffffu, dpw, 1);
        if ((tid & 1) == 0) g_dpw[tileBase + lr] = d2;
    }

    // epilogue: tanh(+b) * hout, reduce over 128 cols (scratch aliases sAh[0])
    float* sred = (float*)&sAh[0][0];
    float ev[2][2] = {{0.f, 0.f}, {0.f, 0.f}};
#pragma unroll
    for (int am = 0; am < 2; am++) {
        size_t gr0 = tileBase + warpM * 32 + am * 16 + (lane >> 2);
        size_t gr1 = gr0 + 8;
        const float* h0p = hout + (size_t)(gr0 & (BN - 1)) * H_;
        const float* h1p = hout + (size_t)(gr1 & (BN - 1)) * H_;
#pragma unroll
        for (int bn = 0; bn < 8; bn++) {
            int col = warpN * 64 + bn * 8 + (lane & 3) * 2;
            float2 bb = *(const float2*)(attn_b + col);
            float2 h0 = *(const float2*)(h0p + col);
            float2 h1 = *(const float2*)(h1p + col);
            ev[am][0] += tanhf(acc[am][bn][0] + bb.x) * h0.x
                       + tanhf(acc[am][bn][1] + bb.y) * h0.y;
            ev[am][1] += tanhf(acc[am][bn][2] + bb.x) * h1.x
                       + tanhf(acc[am][bn][3] + bb.y) * h1.y;
        }
    }
#pragma unroll
    for (int am = 0; am < 2; am++)
#pragma unroll
        for (int rp = 0; rp < 2; rp++) {
            ev[am][rp] += __shfl_xor_sync(0xffffffffu, ev[am][rp], 1);
            ev[am][rp] += __shfl_xor_sync(0xffffffffu, ev[am][rp], 2);
        }
    if (warpN == 1 && (lane & 3) == 0) {
#pragma unroll
        for (int am = 0; am < 2; am++)
#pragma unroll
            for (int rp = 0; rp < 2; rp++)
                sred[((warpM * 2 + am) * 2 + rp) * 8 + (lane >> 2)] = ev[am][rp];
    }
    __syncthreads();
    if (warpN == 0 && (lane & 3) == 0) {
#pragma unroll
        for (int am = 0; am < 2; am++)
#pragma unroll
            for (int rp = 0; rp < 2; rp++) {
                size_t gr = tileBase + warpM * 32 + am * 16 + rp * 8 + (lane >> 2);
                g_energy[gr] = ev[am][rp]
                    + sred[((warpM * 2 + am) * 2 + rp) * 8 + (lane >> 2)];
            }
    }
}

// ---------------- softmax over S + attw + final projection -----------------
__global__ void softmax_out_kernel(const float* __restrict__ proj_w,
                                   const float* __restrict__ proj_b,
                                   const float* __restrict__ hout,
                                   float* __restrict__ out0,
                                   float* __restrict__ attw) {
    int gwarp = (blockIdx.x * blockDim.x + threadIdx.x) >> 5;
    int lane = threadIdx.x & 31;
    if (gwarp >= BN) return;
    int bn = gwarp;

    float e = (lane < S_) ? g_energy[lane * BN + bn] : -1e30f;
    float m = e;
#pragma unroll
    for (int off = 16; off > 0; off >>= 1)
        m = fmaxf(m, __shfl_xor_sync(0xffffffffu, m, off));
    float p = (lane < S_) ? expf(e - m) : 0.f;
    float s = p;
#pragma unroll
    for (int off = 16; off > 0; off >>= 1)
        s += __shfl_xor_sync(0xffffffffu, s, off);
    float a = p / s;
    if (lane < S_) attw[(size_t)bn * S_ + lane] = a;

    float acc = (lane < S_) ? a * g_dpw[lane * BN + bn] : 0.f;
#pragma unroll
    for (int j = 0; j < 4; j++) {
        int col = lane + j * 32;
        acc += hout[(size_t)bn * H_ + col] * proj_w[col];
    }
#pragma unroll
    for (int off = 16; off > 0; off >>= 1)
        acc += __shfl_xor_sync(0xffffffffu, acc, off);
    if (lane == 0) out0[bn] = acc + proj_b[0];
}

// ---------------- orchestration: kernel launches ONLY ----------------------
extern "C" void kernel_launch(void* const* d_in, const int* in_sizes, int n_in,
                              void* d_out, int out_size) {
    const float* inputs  = (const float*)d_in[0];
    const float* enc     = (const float*)d_in[1];
    const float* hidden  = (const float*)d_in[2];
    const float* cell    = (const float*)d_in[3];
    const float* sup     = (const float*)d_in[4];
    const float* w0      = (const float*)d_in[5];
    const float* b0      = (const float*)d_in[6];
    const float* w1      = (const float*)d_in[7];
    const float* b1      = (const float*)d_in[8];
    const float* attn_w  = (const float*)d_in[9];
    const float* attn_b  = (const float*)d_in[10];
    const float* proj_w  = (const float*)d_in[11];
    const float* proj_b  = (const float*)d_in[12];
    float* out = (float*)d_out;

    float* hs0 = out + HS_OFF;
    float* hs1 = out + HS_OFF + (size_t)BN * H_;
    float* cs0 = out + CS_OFF;
    float* cs1 = out + CS_OFF + (size_t)BN * H_;
    float* attw = out + ATT_OFF;

    // launch index 3 = gates_mma layer0 (ncu samples index 3)
    setup_kernel<<<19264, 256>>>(inputs, hidden, hidden + (size_t)BN * H_,
                                 sup, w0, w1, attn_w);                         // 0
    spmmv_kernel<<<dim3(N_, B_ / 4), 128>>>(0, K0_LDA, 0, 132, -1, 132, 0);    // 1
    spmmv_kernel<<<dim3(N_, B_ / 4), 128>>>(0, K0_LDA, 132, 264, 0, 132, 1);   // 2
    gates_mma_kernel<<<dim3(4, BN / 64), 256>>>(b0, cell, hs0, cs0,
                                                K0_LDA, NKT0, NKT0_LOOP, 0);   // 3
    spmmv_kernel<<<dim3(N_, B_ / 4), 128>>>(1, K1_LDA, 0, 256, -1, 256, 0);    // 4
    spmmv_kernel<<<dim3(N_, B_ / 4), 128>>>(1, K1_LDA, 256, 512, 0, 256, 1);   // 5
    gates_mma_kernel<<<dim3(4, BN / 64), 256>>>(b1, cell + (size_t)BN * H_,
                                                hs1, cs1,
                                                K1_LDA, NKT1, NKT1, 1);        // 6
    energy_mma_kernel<<<(S_ * BN) / 128, 256>>>(enc, attn_b, proj_w, hs1);     // 7
    softmax_out_kernel<<<BN / 8, 256>>>(proj_w, proj_b, hs1, out, attw);       // 8
}

// round 14
// speedup vs baseline: 1.1773x; 1.1773x over previous
#include <cuda_runtime.h>
#include <cuda_fp16.h>
#include <cuda_bf16.h>
#include <cstdint>

#define B_   64
#define N_   1024
#define BN   65536
#define H_   128
#define S_   12
#define CSR_CAP 512

#define NGATE   512
#define K0_LDA  448      // layer0 cols: x0[h|x|pad]@0..131, x1@132, x2@264, tail 396..447 zero
#define K1_LDA  768      // layer1 cols: x0@0(256: h_new|h1) x1@256 x2@512
#define NKT0    28       // B-frag layout stride for layer0
#define NKT0_LOOP 25     // cols 400..447 are all-zero -> skip 3 K-tiles
#define NKT1    48

// d_out layout: [output 65536][hs 2*BN*H][cs 2*BN*H][attw BN*S]
#define HS_OFF   65536
#define CS_OFF   (65536 + 2 * BN * H_)
#define ATT_OFF  (CS_OFF + 2 * BN * H_)

// ---------------- scratch (device globals; zero-initialized) ---------------
__device__ float g_feats [(size_t)BN * K0_LDA];
__device__ float g_feats2[(size_t)BN * K1_LDA];
__device__ float g_energy[S_ * BN];
__device__ float g_dpw[S_ * BN];
__device__ int   g_csr_cnt[N_];
__device__ int   g_csr_col[(size_t)N_ * CSR_CAP];
__device__ float g_csr_val[(size_t)N_ * CSR_CAP];
// fp16 single-plane weights, mma-fragment-linear
__device__ __half g_wt0[(size_t)512 * K0_LDA];
__device__ __half g_wt1[(size_t)512 * K1_LDA];
__device__ __half g_aw [(size_t)128 * 128];    // attn_w^T [n][k], fp16

__device__ __forceinline__ float sigmoidf_(float x) { return 1.f / (1.f + expf(-x)); }

__device__ __forceinline__ uint32_t smem_u32(const void* p) {
    uint32_t a;
    asm("{ .reg .u64 t; cvta.to.shared.u64 t, %1; cvt.u32.u64 %0, t; }"
        : "=r"(a) : "l"(p));
    return a;
}
__device__ __forceinline__ void ldsm_x4(uint32_t* r, uint32_t addr) {
    asm volatile("ldmatrix.sync.aligned.m8n8.x4.shared.b16 {%0,%1,%2,%3}, [%4];"
                 : "=r"(r[0]), "=r"(r[1]), "=r"(r[2]), "=r"(r[3]) : "r"(addr));
}
__device__ __forceinline__ void mma_f16(float* d, const uint32_t* a,
                                        const uint32_t* b) {
    asm volatile(
        "mma.sync.aligned.m16n8k16.row.col.f32.f16.f16.f32 "
        "{%0,%1,%2,%3}, {%4,%5,%6,%7}, {%8,%9}, {%0,%1,%2,%3};"
        : "+f"(d[0]), "+f"(d[1]), "+f"(d[2]), "+f"(d[3])
        : "r"(a[0]), "r"(a[1]), "r"(a[2]), "r"(a[3]), "r"(b[0]), "r"(b[1]));
}

// ---- B-fragment addressing: tile(nt2 16-cols, kt) ; regs b0e,b1e,b0o,b1o --
__device__ __forceinline__ size_t bfrag_idx(int k, int n, int nkt) {
    int nt2 = n >> 4, half = (n >> 3) & 1, kt = k >> 4, kk = k & 15;
    return ((size_t)nt2 * nkt + kt) * 256
         + (size_t)(((n & 7) << 2) | ((kk >> 1) & 3)) * 8
         + (size_t)((half << 1) | (kk >> 3)) * 2 + (kk & 1);
}

// ---------------- fused setup: csr + fills + weight splits -----------------
// block ranges: [0,128) csr | [128,8576) fill_x0_l0 | [8576,9472) wsplit0
// [9472,11008) wsplit1 | [11008,11072) awsplit | [11072,19264) fill_h1
__global__ __launch_bounds__(256) void setup_kernel(
    const float* __restrict__ inputs, const float* __restrict__ h0,
    const float* __restrict__ h1, const float* __restrict__ sup,
    const float* __restrict__ w0, const float* __restrict__ w1,
    const float* __restrict__ aw) {
    int blk = blockIdx.x;
    int tid = threadIdx.x;
    if (blk < 128) {
        int n = blk * 8 + (tid >> 5);
        int lane = tid & 31;
        const float* row = sup + (size_t)n * N_;
        int cnt = 0;
        for (int base = 0; base < N_; base += 32) {
            float v = row[base + lane];
            unsigned mask = __ballot_sync(0xffffffffu, v != 0.f);
            if (v != 0.f) {
                int pos = cnt + __popc(mask & ((1u << lane) - 1u));
                if (pos < CSR_CAP) {
                    g_csr_col[n * CSR_CAP + pos] = base + lane;
                    g_csr_val[n * CSR_CAP + pos] = v;
                }
            }
            cnt += __popc(mask);
        }
        if (lane == 0) g_csr_cnt[n] = cnt < CSR_CAP ? cnt : CSR_CAP;
    } else if (blk < 8576) {
        int t = (blk - 128) * 256 + tid;
        if (t >= BN * 33) return;
        int r = t / 33, u = t - r * 33;
        float* dst = g_feats + (size_t)r * K0_LDA;
        if (u < 32) {
            ((float4*)dst)[u] = ((const float4*)(h0 + (size_t)r * H_))[u];
        } else {
            dst[128] = inputs[r];
            dst[129] = 0.f; dst[130] = 0.f; dst[131] = 0.f;
        }
    } else if (blk < 9472) {
        int t = (blk - 8576) * 256 + tid;
        if (t >= 512 * K0_LDA) return;
        int n_il = t / K0_LDA, k = t - n_il * K0_LDA;
        int n = (n_il & 3) * 128 + (n_il >> 2);
        int r = -1;
        if (k < 396) {
            int seg = (k * 0x3E1) >> 17;          // k/132 for k<396
            int p = k - seg * 132;
            int f = (p < 128) ? p + 1 : (p == 128 ? 0 : -1);
            if (f >= 0) r = seg * 129 + f;
        }
        float v = (r >= 0) ? w0[(size_t)r * NGATE + n] : 0.f;
        g_wt0[bfrag_idx(k, n_il, NKT0)] = __float2half_rn(v);
    } else if (blk < 11008) {
        int t = (blk - 9472) * 256 + tid;
        if (t >= 512 * K1_LDA) return;
        int n_il = t / K1_LDA, k = t - n_il * K1_LDA;
        int n = (n_il & 3) * 128 + (n_il >> 2);
        float v = w1[(size_t)k * NGATE + n];
        g_wt1[bfrag_idx(k, n_il, NKT1)] = __float2half_rn(v);
    } else if (blk < 11072) {
        int t = (blk - 11008) * 256 + tid;
        int n = t >> 7, k = t & 127;
        g_aw[t] = __float2half_rn(aw[k * 128 + n]);
    } else {
        int t = (blk - 11072) * 256 + tid;
        if (t >= BN * 32) return;
        int r = t >> 5, u = t & 31;
        ((float4*)(g_feats2 + (size_t)r * K1_LDA + 128))[u] =
            ((const float4*)(h1 + (size_t)r * H_))[u];
    }
}

// ---------------- vectorized sparse diffusion (fp32 only) ------------------
__global__ __launch_bounds__(128) void spmmv_kernel(int buf, int ld, int srcCol,
                                                    int dstCol, int prevCol,
                                                    int D4, int cheb) {
    __shared__ int   scol[CSR_CAP];   // pre-multiplied by ld
    __shared__ float sval[CSR_CAP];
    float* F = buf ? g_feats2 : g_feats;
    int n = blockIdx.x;
    int tid = threadIdx.x, bq = tid >> 5, tq = tid & 31;
    int cnt = g_csr_cnt[n];
    for (int i = tid; i < cnt; i += 128) {
        scol[i] = g_csr_col[n * CSR_CAP + i] * ld;
        sval[i] = g_csr_val[n * CSR_CAP + i];
    }
    __syncthreads();
    int b = blockIdx.y * 4 + bq;
    const float* srcB = F + (size_t)b * N_ * ld + srcCol;
    size_t rbase = ((size_t)b * N_ + n) * ld;
    for (int d0 = tq * 4; d0 < D4; d0 += 128) {
        float4 acc = make_float4(0.f, 0.f, 0.f, 0.f);
        for (int i = 0; i < cnt; i++) {
            const float4 v = *(const float4*)(srcB + scol[i] + d0);
            float s = sval[i];
            acc.x += s * v.x; acc.y += s * v.y; acc.z += s * v.z; acc.w += s * v.w;
        }
        if (cheb) {
            float4 p = *(const float4*)(F + rbase + prevCol + d0);
            acc.x = 2.f * acc.x - p.x; acc.y = 2.f * acc.y - p.y;
            acc.z = 2.f * acc.z - p.z; acc.w = 2.f * acc.w - p.w;
        }
        *(float4*)(F + rbase + dstCol + d0) = acc;
    }
}

// ---------------- gates GEMM + fused LSTM: fp16 SINGLE-product -------------
// Block 64x128, 8 warps (2x4), warp tile 32x32, 2 CTA/SM. R12 structure.
// A: fp32 direct loads (fragment-addressed float2), converted fp16 on load.
// B: single fp16 fragment-linear plane. Per kt per warp: 10 LDG + 8 HMMA.
__global__ __launch_bounds__(256, 2) void gates_mma_kernel(
    const float* __restrict__ bias, const float* __restrict__ c_in,
    float* __restrict__ h_out, float* __restrict__ c_out,
    int lda, int nktLayout, int nktLoop, int layer) {
    const float* F = layer ? g_feats2 : g_feats;
    const uint4* BW = layer ? (const uint4*)g_wt1 : (const uint4*)g_wt0;

    int tid = threadIdx.x, lane = tid & 31, wid = tid >> 5;
    int warpM = wid & 1, warpN = wid >> 1;       // 2 x 4
    int colBase = blockIdx.x * 128;              // col fastest: A reuse in L2
    size_t rowBase = (size_t)blockIdx.y * 64;

    const float* aRow[4];
#pragma unroll
    for (int j = 0; j < 4; j++)
        aRow[j] = F + (rowBase + warpM * 32 + (lane >> 2) + j * 8) * (size_t)lda
                    + (lane & 3) * 2;

    size_t tstride = (size_t)nktLayout * 32;
    size_t bOff0 = ((size_t)(colBase >> 4) + (size_t)warpN * 2) * tstride + lane;
    size_t bOff1 = bOff0 + tstride;

    float acc[2][2][2][4];
#pragma unroll
    for (int i = 0; i < 2; i++)
#pragma unroll
        for (int j = 0; j < 2; j++)
#pragma unroll
            for (int k = 0; k < 2; k++)
#pragma unroll
                for (int q = 0; q < 4; q++) acc[i][j][k][q] = 0.f;

    uint32_t aF[2][2][4];          // [buf][rt][frag reg] fp16x2
    uint4    vB[2][2];             // [buf][nt2]

    auto loadbuf = [&](int bf, int kt) {
        int c0 = kt * 16;
#pragma unroll
        for (int j = 0; j < 4; j++) {
            float2 v0 = *(const float2*)(aRow[j] + c0);
            float2 v1 = *(const float2*)(aRow[j] + c0 + 8);
            __half2 h0 = __floats2half2_rn(v0.x, v0.y);
            __half2 h1 = __floats2half2_rn(v1.x, v1.y);
            int rt = j >> 1, rj = j & 1;
            aF[bf][rt][0 * 2 + rj] = *(uint32_t*)&h0;
            aF[bf][rt][1 * 2 + rj] = *(uint32_t*)&h1;
        }
        size_t ko = (size_t)kt * 32;
        vB[bf][0] = BW[bOff0 + ko];
        vB[bf][1] = BW[bOff1 + ko];
    };
    auto domma = [&](int bf) {
#pragma unroll
        for (int rt = 0; rt < 2; rt++)
#pragma unroll
            for (int nt = 0; nt < 2; nt++) {
                const uint32_t* b = (const uint32_t*)&vB[bf][nt];
                mma_f16(acc[rt][nt][0], aF[bf][rt], b);
                mma_f16(acc[rt][nt][1], aF[bf][rt], b + 2);
            }
    };

    loadbuf(0, 0);
    for (int kt = 0; kt < nktLoop; kt++) {
        int cur = kt & 1;
        if (kt + 1 < nktLoop) loadbuf(cur ^ 1, kt + 1);
        domma(cur);
    }

    // ---- fused LSTM epilogue (col c = 4h+g; lane-pair shuffle) ----
    int evenp = (lane & 1) == 0;
#pragma unroll
    for (int rt = 0; rt < 2; rt++) {
#pragma unroll
        for (int rp = 0; rp < 2; rp++) {
            size_t row = rowBase + warpM * 32 + rt * 16 + rp * 8 + (lane >> 2);
#pragma unroll
            for (int nt = 0; nt < 2; nt++) {
#pragma unroll
                for (int hf = 0; hf < 2; hf++) {
                    int cbase = colBase + warpN * 32 + nt * 16 + hf * 8 + (lane & 3) * 2;
                    int h = cbase >> 2;
                    float a0 = acc[rt][nt][hf][rp * 2 + 0];
                    float a1 = acc[rt][nt][hf][rp * 2 + 1];
                    float v0, v1;
                    if (evenp) {
                        v0 = sigmoidf_(a0 + __ldg(bias + h));          // i
                        v1 = sigmoidf_(a1 + __ldg(bias + 128 + h));    // f
                    } else {
                        v0 = sigmoidf_(a0 + __ldg(bias + 256 + h));    // o
                        v1 = tanhf(a1 + __ldg(bias + 384 + h));        // g
                    }
                    float ex = __shfl_xor_sync(0xffffffffu, v1, 1);
                    float tn = 0.f;
                    if (evenp) {
                        float cin = c_in[row * H_ + h];
                        float cn = v1 * cin + v0 * ex;                 // f*c + i*g
                        c_out[row * H_ + h] = cn;
                        tn = tanhf(cn);
                    }
                    float t2 = __shfl_xor_sync(0xffffffffu, tn, 1);
                    if (!evenp) {
                        float hv = v0 * t2;                            // o*tanh(cn)
                        h_out[row * H_ + h] = hv;
                        if (layer == 0)
                            g_feats2[row * (size_t)K1_LDA + h] = hv;
                    }
                }
            }
        }
    }
}

// ---------------- mma attention energy + dpw (fp16 2-product, smem) --------
#define SROW 12
#define STAGE_U32 (128 * SROW)
__global__ __launch_bounds__(256) void energy_mma_kernel(
    const float* __restrict__ enc, const float* __restrict__ attn_b,
    const float* __restrict__ proj_w, const float* __restrict__ hout) {
    __shared__ __align__(16) uint32_t sAh[2][STAGE_U32];
    __shared__ __align__(16) uint32_t sAl[2][STAGE_U32];
    __shared__ __align__(16) uint32_t sB [2][STAGE_U32];

    int tid = threadIdx.x, lane = tid & 31, wid = tid >> 5;
    int warpM = wid & 3, warpN = wid >> 2;
    size_t tileBase = (size_t)blockIdx.x * 128;

    uint32_t aAH[2], aAL[2], bAd[4];
#pragma unroll
    for (int am = 0; am < 2; am++) {
        int r = warpM * 32 + am * 16 + (lane & 15);
        int c = (lane >> 4) * 4;
        aAH[am] = smem_u32(&sAh[0][r * SROW + c]);
        aAL[am] = smem_u32(&sAl[0][r * SROW + c]);
    }
#pragma unroll
    for (int p = 0; p < 4; p++) {
        int quad = lane >> 3;
        int rowo = ((quad == 0 || quad == 1) ? 0 : 8) + (lane & 7);
        int c = (quad & 1) * 4;
        int n = warpN * 64 + p * 16 + rowo;
        bAd[p] = smem_u32(&sB[0][n * SROW + c]);
    }

    float acc[2][8][4];
#pragma unroll
    for (int i = 0; i < 2; i++)
#pragma unroll
        for (int j = 0; j < 8; j++)
#pragma unroll
            for (int q = 0; q < 4; q++) acc[i][j][q] = 0.f;

    int lr = tid >> 1;
    int lh = (tid & 1) * 8;
    const float* aSrc = enc + (tileBase + lr) * (size_t)H_ + lh;
    const uint4* bSrc = (const uint4*)(g_aw + (size_t)lr * 128 + lh);
    int dstIdx = lr * SROW + (lh >> 1);

    float dpw = 0.f;

    float4 pv0 = ((const float4*)aSrc)[0];
    float4 pv1 = ((const float4*)aSrc)[1];
    uint4 pb = bSrc[0];

    const int nch = H_ / 16;  // 8
    for (int kc = 0; kc < nch; kc++) {
        int st = kc & 1;
        {
            float vv[8] = {pv0.x, pv0.y, pv0.z, pv0.w, pv1.x, pv1.y, pv1.z, pv1.w};
            const float4* pwp = (const float4*)(proj_w + 128 + kc * 16 + lh);
            float4 w0 = __ldg(pwp), w1 = __ldg(pwp + 1);
            dpw += vv[0] * w0.x + vv[1] * w0.y + vv[2] * w0.z + vv[3] * w0.w
                 + vv[4] * w1.x + vv[5] * w1.y + vv[6] * w1.z + vv[7] * w1.w;
            uint32_t hh[4], ll[4];
#pragma unroll
            for (int i = 0; i < 4; i++) {
                float x = vv[2 * i], y = vv[2 * i + 1];
                __half2 hp = __floats2half2_rn(x, y);
                float2 hb = __half22float2(hp);
                __half2 lp = __floats2half2_rn(x - hb.x, y - hb.y);
                hh[i] = *(uint32_t*)&hp;
                ll[i] = *(uint32_t*)&lp;
            }
            *(uint4*)&sAh[st][dstIdx] = make_uint4(hh[0], hh[1], hh[2], hh[3]);
            *(uint4*)&sAl[st][dstIdx] = make_uint4(ll[0], ll[1], ll[2], ll[3]);
            *(uint4*)&sB [st][dstIdx] = pb;
        }
        __syncthreads();
        if (kc + 1 < nch) {
            const float4* s = (const float4*)(aSrc + (kc + 1) * 16);
            pv0 = s[0]; pv1 = s[1];
            pb = bSrc[(kc + 1) * 2];
        }
        uint32_t soff = st * (STAGE_U32 * 4);

        uint32_t aH[2][4], aL[2][4], bv[4][4];
#pragma unroll
        for (int am = 0; am < 2; am++) {
            ldsm_x4(aH[am], aAH[am] + soff);
            ldsm_x4(aL[am], aAL[am] + soff);
        }
#pragma unroll
        for (int p = 0; p < 4; p++)
            ldsm_x4(bv[p], bAd[p] + soff);

#pragma unroll
        for (int am = 0; am < 2; am++) {
#pragma unroll
            for (int p = 0; p < 4; p++) {
                mma_f16(acc[am][2 * p],     aH[am], &bv[p][0]);
                mma_f16(acc[am][2 * p],     aL[am], &bv[p][0]);
                mma_f16(acc[am][2 * p + 1], aH[am], &bv[p][2]);
                mma_f16(acc[am][2 * p + 1], aL[am], &bv[p][2]);
            }
        }
    }

    {
        float d2 = dpw + __shfl_xor_sync(0xffffffffu, dpw, 1);
        if ((tid & 1) == 0) g_dpw[tileBase + lr] = d2;
    }

    // epilogue: tanh(+b) * hout, reduce over 128 cols (scratch aliases sAh[0])
    float* sred = (float*)&sAh[0][0];
    float ev[2][2] = {{0.f, 0.f}, {0.f, 0.f}};
#pragma unroll
    for (int am = 0; am < 2; am++) {
        size_t gr0 = tileBase + warpM * 32 + am * 16 + (lane >> 2);
        size_t gr1 = gr0 + 8;
        const float* h0p = hout + (size_t)(gr0 & (BN - 1)) * H_;
        const float* h1p = hout + (size_t)(gr1 & (BN - 1)) * H_;
#pragma unroll
        for (int bn = 0; bn < 8; bn++) {
            int col = warpN * 64 + bn * 8 + (lane & 3) * 2;
            float2 bb = *(const float2*)(attn_b + col);
            float2 h0 = *(const float2*)(h0p + col);
            float2 h1 = *(const float2*)(h1p + col);
            ev[am][0] += tanhf(acc[am][bn][0] + bb.x) * h0.x
                       + tanhf(acc[am][bn][1] + bb.y) * h0.y;
            ev[am][1] += tanhf(acc[am][bn][2] + bb.x) * h1.x
                       + tanhf(acc[am][bn][3] + bb.y) * h1.y;
        }
    }
#pragma unroll
    for (int am = 0; am < 2; am++)
#pragma unroll
        for (int rp = 0; rp < 2; rp++) {
            ev[am][rp] += __shfl_xor_sync(0xffffffffu, ev[am][rp], 1);
            ev[am][rp] += __shfl_xor_sync(0xffffffffu, ev[am][rp], 2);
        }
    if (warpN == 1 && (lane & 3) == 0) {
#pragma unroll
        for (int am = 0; am < 2; am++)
#pragma unroll
            for (int rp = 0; rp < 2; rp++)
                sred[((warpM * 2 + am) * 2 + rp) * 8 + (lane >> 2)] = ev[am][rp];
    }
    __syncthreads();
    if (warpN == 0 && (lane & 3) == 0) {
#pragma unroll
        for (int am = 0; am < 2; am++)
#pragma unroll
            for (int rp = 0; rp < 2; rp++) {
                size_t gr = tileBase + warpM * 32 + am * 16 + rp * 8 + (lane >> 2);
                g_energy[gr] = ev[am][rp]
                    + sred[((warpM * 2 + am) * 2 + rp) * 8 + (lane >> 2)];
            }
    }
}

// ---------------- softmax over S + attw + final projection -----------------
__global__ void softmax_out_kernel(const float* __restrict__ proj_w,
                                   const float* __restrict__ proj_b,
                                   const float* __restrict__ hout,
                                   float* __restrict__ out0,
                                   float* __restrict__ attw) {
    int gwarp = (blockIdx.x * blockDim.x + threadIdx.x) >> 5;
    int lane = threadIdx.x & 31;
    if (gwarp >= BN) return;
    int bn = gwarp;

    float e = (lane < S_) ? g_energy[lane * BN + bn] : -1e30f;
    float m = e;
#pragma unroll
    for (int off = 16; off > 0; off >>= 1)
        m = fmaxf(m, __shfl_xor_sync(0xffffffffu, m, off));
    float p = (lane < S_) ? expf(e - m) : 0.f;
    float s = p;
#pragma unroll
    for (int off = 16; off > 0; off >>= 1)
        s += __shfl_xor_sync(0xffffffffu, s, off);
    float a = p / s;
    if (lane < S_) attw[(size_t)bn * S_ + lane] = a;

    float acc = (lane < S_) ? a * g_dpw[lane * BN + bn] : 0.f;
#pragma unroll
    for (int j = 0; j < 4; j++) {
        int col = lane + j * 32;
        acc += hout[(size_t)bn * H_ + col] * proj_w[col];
    }
#pragma unroll
    for (int off = 16; off > 0; off >>= 1)
        acc += __shfl_xor_sync(0xffffffffu, acc, off);
    if (lane == 0) out0[bn] = acc + proj_b[0];
}

// ---------------- orchestration: kernel launches ONLY ----------------------
extern "C" void kernel_launch(void* const* d_in, const int* in_sizes, int n_in,
                              void* d_out, int out_size) {
    const float* inputs  = (const float*)d_in[0];
    const float* enc     = (const float*)d_in[1];
    const float* hidden  = (const float*)d_in[2];
    const float* cell    = (const float*)d_in[3];
    const float* sup     = (const float*)d_in[4];
    const float* w0      = (const float*)d_in[5];
    const float* b0      = (const float*)d_in[6];
    const float* w1      = (const float*)d_in[7];
    const float* b1      = (const float*)d_in[8];
    const float* attn_w  = (const float*)d_in[9];
    const float* attn_b  = (const float*)d_in[10];
    const float* proj_w  = (const float*)d_in[11];
    const float* proj_b  = (const float*)d_in[12];
    float* out = (float*)d_out;

    float* hs0 = out + HS_OFF;
    float* hs1 = out + HS_OFF + (size_t)BN * H_;
    float* cs0 = out + CS_OFF;
    float* cs1 = out + CS_OFF + (size_t)BN * H_;
    float* attw = out + ATT_OFF;

    // launch index 3 = gates_mma layer0 (ncu samples index 3)
    setup_kernel<<<19264, 256>>>(inputs, hidden, hidden + (size_t)BN * H_,
                                 sup, w0, w1, attn_w);                         // 0
    spmmv_kernel<<<dim3(N_, B_ / 4), 128>>>(0, K0_LDA, 0, 132, -1, 132, 0);    // 1
    spmmv_kernel<<<dim3(N_, B_ / 4), 128>>>(0, K0_LDA, 132, 264, 0, 132, 1);   // 2
    gates_mma_kernel<<<dim3(4, BN / 64), 256>>>(b0, cell, hs0, cs0,
                                                K0_LDA, NKT0, NKT0_LOOP, 0);   // 3
    spmmv_kernel<<<dim3(N_, B_ / 4), 128>>>(1, K1_LDA, 0, 256, -1, 256, 0);    // 4
    spmmv_kernel<<<dim3(N_, B_ / 4), 128>>>(1, K1_LDA, 256, 512, 0, 256, 1);   // 5
    gates_mma_kernel<<<dim3(4, BN / 64), 256>>>(b1, cell + (size_t)BN * H_,
                                                hs1, cs1,
                                                K1_LDA, NKT1, NKT1, 1);        // 6
    energy_mma_kernel<<<(S_ * BN) / 128, 256>>>(enc, attn_b, proj_w, hs1);     // 7
    softmax_out_kernel<<<BN / 8, 256>>>(proj_w, proj_b, hs1, out, attw);       // 8
}

// round 15
// speedup vs baseline: 1.4618x; 1.2417x over previous
#include <cuda_runtime.h>
#include <cuda_fp16.h>
#include <cuda_bf16.h>
#include <cstdint>

#define B_   64
#define N_   1024
#define BN   65536
#define H_   128
#define S_   12
#define CSR_CAP 512

#define NGATE   512
#define K0_LDA  448      // layer0 cols: x0[h|x|pad]@0..131, x1@132, x2@264, tail 396..447 zero
#define K1_LDA  768      // layer1 cols: x0@0(256: h_new|h1) x1@256 x2@512
#define NKT0    28       // frag layout stride (tiles) for layer0
#define NKT0_LOOP 25     // cols 400..447 all-zero -> skip 3 K-tiles
#define NKT1    48

// d_out layout: [output 65536][hs 2*BN*H][cs 2*BN*H][attw BN*S]
#define HS_OFF   65536
#define CS_OFF   (65536 + 2 * BN * H_)
#define ATT_OFF  (CS_OFF + 2 * BN * H_)

// ---------------- scratch (device globals; zero-initialized) ---------------
__device__ float g_feats [(size_t)BN * K0_LDA];   // fp32 (spmm gather chain)
__device__ float g_feats2[(size_t)BN * K1_LDA];
__device__ float g_energy[S_ * BN];
__device__ float g_dpw[S_ * BN];
__device__ int   g_csr_cnt[N_];
__device__ int   g_csr_col[(size_t)N_ * CSR_CAP];
__device__ float g_csr_val[(size_t)N_ * CSR_CAP];
// fp16 single-plane A operands, mma-fragment-linear (16x16 tiles, 512B, uint4/lane)
__device__ __half g_af0[(size_t)BN * K0_LDA];
__device__ __half g_af1[(size_t)BN * K1_LDA];
// fp16 single-plane weights, mma-fragment-linear
__device__ __half g_wt0[(size_t)512 * K0_LDA];
__device__ __half g_wt1[(size_t)512 * K1_LDA];
__device__ __half g_aw [(size_t)128 * 128];    // attn_w^T [n][k], fp16

__device__ __forceinline__ float sigmoidf_(float x) { return 1.f / (1.f + expf(-x)); }

__device__ __forceinline__ uint32_t smem_u32(const void* p) {
    uint32_t a;
    asm("{ .reg .u64 t; cvta.to.shared.u64 t, %1; cvt.u32.u64 %0, t; }"
        : "=r"(a) : "l"(p));
    return a;
}
__device__ __forceinline__ void ldsm_x4(uint32_t* r, uint32_t addr) {
    asm volatile("ldmatrix.sync.aligned.m8n8.x4.shared.b16 {%0,%1,%2,%3}, [%4];"
                 : "=r"(r[0]), "=r"(r[1]), "=r"(r[2]), "=r"(r[3]) : "r"(addr));
}
__device__ __forceinline__ void mma_f16(float* d, const uint32_t* a,
                                        const uint32_t* b) {
    asm volatile(
        "mma.sync.aligned.m16n8k16.row.col.f32.f16.f16.f32 "
        "{%0,%1,%2,%3}, {%4,%5,%6,%7}, {%8,%9}, {%0,%1,%2,%3};"
        : "+f"(d[0]), "+f"(d[1]), "+f"(d[2]), "+f"(d[3])
        : "r"(a[0]), "r"(a[1]), "r"(a[2]), "r"(a[3]), "r"(b[0]), "r"(b[1]));
}

// ---- A-fragment write: tile(rt,kt) 16x16 fp16, lane-major uint4 ----------
__device__ __forceinline__ void frag_write4(__half* __restrict__ p,
                                            size_t row, int col0, int nkt,
                                            float4 v) {
    int rt = (int)(row >> 4), r = (int)(row & 15);
    int kt = col0 >> 4, cc = col0 & 15;
    int lane0 = ((r & 7) << 2) | ((cc >> 1) & 3);
    int reg = (r >> 3) | ((cc >> 3) << 1);
    size_t base = ((size_t)rt * nkt + kt) * 256 + reg * 2;
    __half2 h01 = __floats2half2_rn(v.x, v.y);
    __half2 h23 = __floats2half2_rn(v.z, v.w);
    *(__half2*)(p + base + lane0 * 8) = h01;
    *(__half2*)(p + base + (lane0 + 1) * 8) = h23;
}
__device__ __forceinline__ void frag_write1(__half* __restrict__ p,
                                            size_t row, int col, int nkt, float v) {
    int rt = (int)(row >> 4), r = (int)(row & 15);
    int kt = col >> 4, cc = col & 15;
    size_t idx = ((size_t)rt * nkt + kt) * 256
               + (size_t)(((r & 7) << 2) | ((cc >> 1) & 3)) * 8
               + (size_t)((r >> 3) | ((cc >> 3) << 1)) * 2 + (cc & 1);
    p[idx] = __float2half_rn(v);
}
// ---- B-fragment addressing ------------------------------------------------
__device__ __forceinline__ size_t bfrag_idx(int k, int n, int nkt) {
    int nt2 = n >> 4, half = (n >> 3) & 1, kt = k >> 4, kk = k & 15;
    return ((size_t)nt2 * nkt + kt) * 256
         + (size_t)(((n & 7) << 2) | ((kk >> 1) & 3)) * 8
         + (size_t)((half << 1) | (kk >> 3)) * 2 + (kk & 1);
}

// ---------------- fused setup: csr + fills + weight splits -----------------
__global__ __launch_bounds__(256) void setup_kernel(
    const float* __restrict__ inputs, const float* __restrict__ h0,
    const float* __restrict__ h1, const float* __restrict__ sup,
    const float* __restrict__ w0, const float* __restrict__ w1,
    const float* __restrict__ aw) {
    int blk = blockIdx.x;
    int tid = threadIdx.x;
    if (blk < 128) {
        int n = blk * 8 + (tid >> 5);
        int lane = tid & 31;
        const float* row = sup + (size_t)n * N_;
        int cnt = 0;
        for (int base = 0; base < N_; base += 32) {
            float v = row[base + lane];
            unsigned mask = __ballot_sync(0xffffffffu, v != 0.f);
            if (v != 0.f) {
                int pos = cnt + __popc(mask & ((1u << lane) - 1u));
                if (pos < CSR_CAP) {
                    g_csr_col[n * CSR_CAP + pos] = base + lane;
                    g_csr_val[n * CSR_CAP + pos] = v;
                }
            }
            cnt += __popc(mask);
        }
        if (lane == 0) g_csr_cnt[n] = cnt < CSR_CAP ? cnt : CSR_CAP;
    } else if (blk < 8576) {
        int t = (blk - 128) * 256 + tid;
        if (t >= BN * 33) return;
        int r = t / 33, u = t - r * 33;
        float* dst = g_feats + (size_t)r * K0_LDA;
        if (u < 32) {
            float4 v = ((const float4*)(h0 + (size_t)r * H_))[u];
            ((float4*)dst)[u] = v;
            frag_write4(g_af0, (size_t)r, u * 4, NKT0, v);
        } else {
            float4 v = make_float4(inputs[r], 0.f, 0.f, 0.f);
            ((float4*)dst)[32] = v;
            frag_write4(g_af0, (size_t)r, 128, NKT0, v);
        }
    } else if (blk < 9472) {
        int t = (blk - 8576) * 256 + tid;
        if (t >= 512 * K0_LDA) return;
        int n_il = t / K0_LDA, k = t - n_il * K0_LDA;
        int n = (n_il & 3) * 128 + (n_il >> 2);
        int r = -1;
        if (k < 396) {
            int seg = (k * 0x3E1) >> 17;          // k/132 for k<396
            int p = k - seg * 132;
            int f = (p < 128) ? p + 1 : (p == 128 ? 0 : -1);
            if (f >= 0) r = seg * 129 + f;
        }
        float v = (r >= 0) ? w0[(size_t)r * NGATE + n] : 0.f;
        g_wt0[bfrag_idx(k, n_il, NKT0)] = __float2half_rn(v);
    } else if (blk < 11008) {
        int t = (blk - 9472) * 256 + tid;
        if (t >= 512 * K1_LDA) return;
        int n_il = t / K1_LDA, k = t - n_il * K1_LDA;
        int n = (n_il & 3) * 128 + (n_il >> 2);
        float v = w1[(size_t)k * NGATE + n];
        g_wt1[bfrag_idx(k, n_il, NKT1)] = __float2half_rn(v);
    } else if (blk < 11072) {
        int t = (blk - 11008) * 256 + tid;
        int n = t >> 7, k = t & 127;
        g_aw[t] = __float2half_rn(aw[k * 128 + n]);
    } else {
        int t = (blk - 11072) * 256 + tid;
        if (t >= BN * 32) return;
        int r = t >> 5, u = t & 31;
        float4 v = ((const float4*)(h1 + (size_t)r * H_))[u];
        ((float4*)(g_feats2 + (size_t)r * K1_LDA + 128))[u] = v;
        frag_write4(g_af1, (size_t)r, 128 + u * 4, NKT1, v);
    }
}

// ---------------- vectorized sparse diffusion + frag output ----------------
__global__ __launch_bounds__(128) void spmmv_kernel(int buf, int ld, int srcCol,
                                                    int dstCol, int prevCol,
                                                    int D4, int cheb,
                                                    int writeF32, int nkt) {
    __shared__ int   scol[CSR_CAP];   // pre-multiplied by ld
    __shared__ float sval[CSR_CAP];
    float* F = buf ? g_feats2 : g_feats;
    __half* AF = buf ? g_af1 : g_af0;
    int n = blockIdx.x;
    int tid = threadIdx.x, bq = tid >> 5, tq = tid & 31;
    int cnt = g_csr_cnt[n];
    for (int i = tid; i < cnt; i += 128) {
        scol[i] = g_csr_col[n * CSR_CAP + i] * ld;
        sval[i] = g_csr_val[n * CSR_CAP + i];
    }
    __syncthreads();
    int b = blockIdx.y * 4 + bq;
    size_t row = (size_t)b * N_ + n;
    const float* srcB = F + (size_t)b * N_ * ld + srcCol;
    size_t rbase = row * ld;
    for (int d0 = tq * 4; d0 < D4; d0 += 128) {
        float4 acc = make_float4(0.f, 0.f, 0.f, 0.f);
        for (int i = 0; i < cnt; i++) {
            const float4 v = *(const float4*)(srcB + scol[i] + d0);
            float s = sval[i];
            acc.x += s * v.x; acc.y += s * v.y; acc.z += s * v.z; acc.w += s * v.w;
        }
        if (cheb) {
            float4 p = *(const float4*)(F + rbase + prevCol + d0);
            acc.x = 2.f * acc.x - p.x; acc.y = 2.f * acc.y - p.y;
            acc.z = 2.f * acc.z - p.z; acc.w = 2.f * acc.w - p.w;
        }
        if (writeF32)
            *(float4*)(F + rbase + dstCol + d0) = acc;
        frag_write4(AF, row, dstCol + d0, nkt, acc);
    }
}

// ---------------- gates GEMM + fused LSTM: frag-A fp16 single-product ------
// Block 64x128, 8 warps (2x4), warp tile 32x32, 2 CTA/SM.
// Per kt per warp: 2 LDG.128 A (frag-linear) + 2 LDG.128 B + 8 HMMA.
__global__ __launch_bounds__(256, 2) void gates_mma_kernel(
    const float* __restrict__ bias, const float* __restrict__ c_in,
    float* __restrict__ h_out, float* __restrict__ c_out,
    int nktLayout, int nktLoop, int layer) {
    const uint4* AF = layer ? (const uint4*)g_af1 : (const uint4*)g_af0;
    const uint4* BW = layer ? (const uint4*)g_wt1 : (const uint4*)g_wt0;

    int tid = threadIdx.x, lane = tid & 31, wid = tid >> 5;
    int warpM = wid & 1, warpN = wid >> 1;       // 2 x 4
    int colBase = blockIdx.x * 128;              // col fastest: A reuse in L2
    size_t rowBase = (size_t)blockIdx.y * 64;

    size_t tstride = (size_t)nktLayout * 32;     // uint4 per 16-row band
    size_t aOff0 = ((rowBase >> 4) + (size_t)warpM * 2) * tstride + lane;
    size_t aOff1 = aOff0 + tstride;
    size_t bOff0 = ((size_t)(colBase >> 4) + (size_t)warpN * 2) * tstride + lane;
    size_t bOff1 = bOff0 + tstride;

    float acc[2][2][2][4];
#pragma unroll
    for (int i = 0; i < 2; i++)
#pragma unroll
        for (int j = 0; j < 2; j++)
#pragma unroll
            for (int k = 0; k < 2; k++)
#pragma unroll
                for (int q = 0; q < 4; q++) acc[i][j][k][q] = 0.f;

    uint4 vA[2][2], vB[2][2];      // [buf][rt/nt]

    auto loadbuf = [&](int bf, int kt) {
        size_t ko = (size_t)kt * 32;
        vA[bf][0] = AF[aOff0 + ko];
        vA[bf][1] = AF[aOff1 + ko];
        vB[bf][0] = BW[bOff0 + ko];
        vB[bf][1] = BW[bOff1 + ko];
    };
    auto domma = [&](int bf) {
#pragma unroll
        for (int rt = 0; rt < 2; rt++) {
            const uint32_t* a = (const uint32_t*)&vA[bf][rt];
#pragma unroll
            for (int nt = 0; nt < 2; nt++) {
                const uint32_t* b = (const uint32_t*)&vB[bf][nt];
                mma_f16(acc[rt][nt][0], a, b);
                mma_f16(acc[rt][nt][1], a, b + 2);
            }
        }
    };

    loadbuf(0, 0);
    for (int kt = 0; kt < nktLoop; kt++) {
        int cur = kt & 1;
        if (kt + 1 < nktLoop) loadbuf(cur ^ 1, kt + 1);
        domma(cur);
    }

    // ---- fused LSTM epilogue (col c = 4h+g; lane-pair shuffle) ----
    int evenp = (lane & 1) == 0;
#pragma unroll
    for (int rt = 0; rt < 2; rt++) {
#pragma unroll
        for (int rp = 0; rp < 2; rp++) {
            size_t row = rowBase + warpM * 32 + rt * 16 + rp * 8 + (lane >> 2);
#pragma unroll
            for (int nt = 0; nt < 2; nt++) {
#pragma unroll
                for (int hf = 0; hf < 2; hf++) {
                    int cbase = colBase + warpN * 32 + nt * 16 + hf * 8 + (lane & 3) * 2;
                    int h = cbase >> 2;
                    float a0 = acc[rt][nt][hf][rp * 2 + 0];
                    float a1 = acc[rt][nt][hf][rp * 2 + 1];
                    float v0, v1;
                    if (evenp) {
                        v0 = sigmoidf_(a0 + __ldg(bias + h));          // i
                        v1 = sigmoidf_(a1 + __ldg(bias + 128 + h));    // f
                    } else {
                        v0 = sigmoidf_(a0 + __ldg(bias + 256 + h));    // o
                        v1 = tanhf(a1 + __ldg(bias + 384 + h));        // g
                    }
                    float ex = __shfl_xor_sync(0xffffffffu, v1, 1);
                    float tn = 0.f;
                    if (evenp) {
                        float cin = c_in[row * H_ + h];
                        float cn = v1 * cin + v0 * ex;                 // f*c + i*g
                        c_out[row * H_ + h] = cn;
                        tn = tanhf(cn);
                    }
                    float t2 = __shfl_xor_sync(0xffffffffu, tn, 1);
                    if (!evenp) {
                        float hv = v0 * t2;                            // o*tanh(cn)
                        h_out[row * H_ + h] = hv;
                        if (layer == 0) {
                            g_feats2[row * (size_t)K1_LDA + h] = hv;
                            frag_write1(g_af1, row, h, NKT1, hv);
                        }
                    }
                }
            }
        }
    }
}

// ---------------- mma attention energy + dpw (fp16 2-product, smem) --------
#define SROW 12
#define STAGE_U32 (128 * SROW)
__global__ __launch_bounds__(256) void energy_mma_kernel(
    const float* __restrict__ enc, const float* __restrict__ attn_b,
    const float* __restrict__ proj_w, const float* __restrict__ hout) {
    __shared__ __align__(16) uint32_t sAh[2][STAGE_U32];
    __shared__ __align__(16) uint32_t sAl[2][STAGE_U32];
    __shared__ __align__(16) uint32_t sB [2][STAGE_U32];

    int tid = threadIdx.x, lane = tid & 31, wid = tid >> 5;
    int warpM = wid & 3, warpN = wid >> 2;
    size_t tileBase = (size_t)blockIdx.x * 128;

    uint32_t aAH[2], aAL[2], bAd[4];
#pragma unroll
    for (int am = 0; am < 2; am++) {
        int r = warpM * 32 + am * 16 + (lane & 15);
        int c = (lane >> 4) * 4;
        aAH[am] = smem_u32(&sAh[0][r * SROW + c]);
        aAL[am] = smem_u32(&sAl[0][r * SROW + c]);
    }
#pragma unroll
    for (int p = 0; p < 4; p++) {
        int quad = lane >> 3;
        int rowo = ((quad == 0 || quad == 1) ? 0 : 8) + (lane & 7);
        int c = (quad & 1) * 4;
        int n = warpN * 64 + p * 16 + rowo;
        bAd[p] = smem_u32(&sB[0][n * SROW + c]);
    }

    float acc[2][8][4];
#pragma unroll
    for (int i = 0; i < 2; i++)
#pragma unroll
        for (int j = 0; j < 8; j++)
#pragma unroll
            for (int q = 0; q < 4; q++) acc[i][j][q] = 0.f;

    int lr = tid >> 1;
    int lh = (tid & 1) * 8;
    const float* aSrc = enc + (tileBase + lr) * (size_t)H_ + lh;
    const uint4* bSrc = (const uint4*)(g_aw + (size_t)lr * 128 + lh);
    int dstIdx = lr * SROW + (lh >> 1);

    float dpw = 0.f;

    float4 pv0 = ((const float4*)aSrc)[0];
    float4 pv1 = ((const float4*)aSrc)[1];
    uint4 pb = bSrc[0];

    const int nch = H_ / 16;  // 8
    for (int kc = 0; kc < nch; kc++) {
        int st = kc & 1;
        {
            float vv[8] = {pv0.x, pv0.y, pv0.z, pv0.w, pv1.x, pv1.y, pv1.z, pv1.w};
            const float4* pwp = (const float4*)(proj_w + 128 + kc * 16 + lh);
            float4 w0 = __ldg(pwp), w1 = __ldg(pwp + 1);
            dpw += vv[0] * w0.x + vv[1] * w0.y + vv[2] * w0.z + vv[3] * w0.w
                 + vv[4] * w1.x + vv[5] * w1.y + vv[6] * w1.z + vv[7] * w1.w;
            uint32_t hh[4], ll[4];
#pragma unroll
            for (int i = 0; i < 4; i++) {
                float x = vv[2 * i], y = vv[2 * i + 1];
                __half2 hp = __floats2half2_rn(x, y);
                float2 hb = __half22float2(hp);
                __half2 lp = __floats2half2_rn(x - hb.x, y - hb.y);
                hh[i] = *(uint32_t*)&hp;
                ll[i] = *(uint32_t*)&lp;
            }
            *(uint4*)&sAh[st][dstIdx] = make_uint4(hh[0], hh[1], hh[2], hh[3]);
            *(uint4*)&sAl[st][dstIdx] = make_uint4(ll[0], ll[1], ll[2], ll[3]);
            *(uint4*)&sB [st][dstIdx] = pb;
        }
        __syncthreads();
        if (kc + 1 < nch) {
            const float4* s = (const float4*)(aSrc + (kc + 1) * 16);
            pv0 = s[0]; pv1 = s[1];
            pb = bSrc[(kc + 1) * 2];
        }
        uint32_t soff = st * (STAGE_U32 * 4);

        uint32_t aH[2][4], aL[2][4], bv[4][4];
#pragma unroll
        for (int am = 0; am < 2; am++) {
            ldsm_x4(aH[am], aAH[am] + soff);
            ldsm_x4(aL[am], aAL[am] + soff);
        }
#pragma unroll
        for (int p = 0; p < 4; p++)
            ldsm_x4(bv[p], bAd[p] + soff);

#pragma unroll
        for (int am = 0; am < 2; am++) {
#pragma unroll
            for (int p = 0; p < 4; p++) {
                mma_f16(acc[am][2 * p],     aH[am], &bv[p][0]);
                mma_f16(acc[am][2 * p],     aL[am], &bv[p][0]);
                mma_f16(acc[am][2 * p + 1], aH[am], &bv[p][2]);
                mma_f16(acc[am][2 * p + 1], aL[am], &bv[p][2]);
            }
        }
    }

    {
        float d2 = dpw + __shfl_xor_sync(0xffffffffu, dpw, 1);
        if ((tid & 1) == 0) g_dpw[tileBase + lr] = d2;
    }

    // epilogue: tanh(+b) * hout, reduce over 128 cols (scratch aliases sAh[0])
    float* sred = (float*)&sAh[0][0];
    float ev[2][2] = {{0.f, 0.f}, {0.f, 0.f}};
#pragma unroll
    for (int am = 0; am < 2; am++) {
        size_t gr0 = tileBase + warpM * 32 + am * 16 + (lane >> 2);
        size_t gr1 = gr0 + 8;
        const float* h0p = hout + (size_t)(gr0 & (BN - 1)) * H_;
        const float* h1p = hout + (size_t)(gr1 & (BN - 1)) * H_;
#pragma unroll
        for (int bn = 0; bn < 8; bn++) {
            int col = warpN * 64 + bn * 8 + (lane & 3) * 2;
            float2 bb = *(const float2*)(attn_b + col);
            float2 h0 = *(const float2*)(h0p + col);
            float2 h1 = *(const float2*)(h1p + col);
            ev[am][0] += tanhf(acc[am][bn][0] + bb.x) * h0.x
                       + tanhf(acc[am][bn][1] + bb.y) * h0.y;
            ev[am][1] += tanhf(acc[am][bn][2] + bb.x) * h1.x
                       + tanhf(acc[am][bn][3] + bb.y) * h1.y;
        }
    }
#pragma unroll
    for (int am = 0; am < 2; am++)
#pragma unroll
        for (int rp = 0; rp < 2; rp++) {
            ev[am][rp] += __shfl_xor_sync(0xffffffffu, ev[am][rp], 1);
            ev[am][rp] += __shfl_xor_sync(0xffffffffu, ev[am][rp], 2);
        }
    if (warpN == 1 && (lane & 3) == 0) {
#pragma unroll
        for (int am = 0; am < 2; am++)
#pragma unroll
            for (int rp = 0; rp < 2; rp++)
                sred[((warpM * 2 + am) * 2 + rp) * 8 + (lane >> 2)] = ev[am][rp];
    }
    __syncthreads();
    if (warpN == 0 && (lane & 3) == 0) {
#pragma unroll
        for (int am = 0; am < 2; am++)
#pragma unroll
            for (int rp = 0; rp < 2; rp++) {
                size_t gr = tileBase + warpM * 32 + am * 16 + rp * 8 + (lane >> 2);
                g_energy[gr] = ev[am][rp]
                    + sred[((warpM * 2 + am) * 2 + rp) * 8 + (lane >> 2)];
            }
    }
}

// ---------------- softmax over S + attw + final projection -----------------
__global__ void softmax_out_kernel(const float* __restrict__ proj_w,
                                   const float* __restrict__ proj_b,
                                   const float* __restrict__ hout,
                                   float* __restrict__ out0,
                                   float* __restrict__ attw) {
    int gwarp = (blockIdx.x * blockDim.x + threadIdx.x) >> 5;
    int lane = threadIdx.x & 31;
    if (gwarp >= BN) return;
    int bn = gwarp;

    float e = (lane < S_) ? g_energy[lane * BN + bn] : -1e30f;
    float m = e;
#pragma unroll
    for (int off = 16; off > 0; off >>= 1)
        m = fmaxf(m, __shfl_xor_sync(0xffffffffu, m, off));
    float p = (lane < S_) ? expf(e - m) : 0.f;
    float s = p;
#pragma unroll
    for (int off = 16; off > 0; off >>= 1)
        s += __shfl_xor_sync(0xffffffffu, s, off);
    float a = p / s;
    if (lane < S_) attw[(size_t)bn * S_ + lane] = a;

    float acc = (lane < S_) ? a * g_dpw[lane * BN + bn] : 0.f;
#pragma unroll
    for (int j = 0; j < 4; j++) {
        int col = lane + j * 32;
        acc += hout[(size_t)bn * H_ + col] * proj_w[col];
    }
#pragma unroll
    for (int off = 16; off > 0; off >>= 1)
        acc += __shfl_xor_sync(0xffffffffu, acc, off);
    if (lane == 0) out0[bn] = acc + proj_b[0];
}

// ---------------- orchestration: kernel launches ONLY ----------------------
extern "C" void kernel_launch(void* const* d_in, const int* in_sizes, int n_in,
                              void* d_out, int out_size) {
    const float* inputs  = (const float*)d_in[0];
    const float* enc     = (const float*)d_in[1];
    const float* hidden  = (const float*)d_in[2];
    const float* cell    = (const float*)d_in[3];
    const float* sup     = (const float*)d_in[4];
    const float* w0      = (const float*)d_in[5];
    const float* b0      = (const float*)d_in[6];
    const float* w1      = (const float*)d_in[7];
    const float* b1      = (const float*)d_in[8];
    const float* attn_w  = (const float*)d_in[9];
    const float* attn_b  = (const float*)d_in[10];
    const float* proj_w  = (const float*)d_in[11];
    const float* proj_b  = (const float*)d_in[12];
    float* out = (float*)d_out;

    float* hs0 = out + HS_OFF;
    float* hs1 = out + HS_OFF + (size_t)BN * H_;
    float* cs0 = out + CS_OFF;
    float* cs1 = out + CS_OFF + (size_t)BN * H_;
    float* attw = out + ATT_OFF;

    // launch index 3 = gates_mma layer0 (ncu samples index 3)
    setup_kernel<<<19264, 256>>>(inputs, hidden, hidden + (size_t)BN * H_,
                                 sup, w0, w1, attn_w);                             // 0
    spmmv_kernel<<<dim3(N_, B_ / 4), 128>>>(0, K0_LDA, 0, 132, -1, 132, 0, 1, NKT0);   // 1
    spmmv_kernel<<<dim3(N_, B_ / 4), 128>>>(0, K0_LDA, 132, 264, 0, 132, 1, 0, NKT0);  // 2
    gates_mma_kernel<<<dim3(4, BN / 64), 256>>>(b0, cell, hs0, cs0,
                                                NKT0, NKT0_LOOP, 0);               // 3
    spmmv_kernel<<<dim3(N_, B_ / 4), 128>>>(1, K1_LDA, 0, 256, -1, 256, 0, 1, NKT1);   // 4
    spmmv_kernel<<<dim3(N_, B_ / 4), 128>>>(1, K1_LDA, 256, 512, 0, 256, 1, 0, NKT1);  // 5
    gates_mma_kernel<<<dim3(4, BN / 64), 256>>>(b1, cell + (size_t)BN * H_,
                                                hs1, cs1, NKT1, NKT1, 1);          // 6
    energy_mma_kernel<<<(S_ * BN) / 128, 256>>>(enc, attn_b, proj_w, hs1);         // 7
    softmax_out_kernel<<<BN / 8, 256>>>(proj_w, proj_b, hs1, out, attw);           // 8
}

// round 16
// speedup vs baseline: 1.6265x; 1.1127x over previous
#include <cuda_runtime.h>
#include <cuda_fp16.h>
#include <cuda_bf16.h>
#include <cstdint>

#define B_   64
#define N_   1024
#define BN   65536
#define H_   128
#define S_   12
#define CSR_CAP 512

#define NGATE   512
#define K0_LDA  448      // layer0 cols: x0[h|x|pad]@0..131, x1@132, x2@264, tail 396..447 zero
#define K1_LDA  768      // layer1 cols: x0@0(256: h_new|h1) x1@256 x2@512
#define NKT0    28       // frag layout stride (tiles) for layer0
#define NKT0_LOOP 25     // cols 400..447 all-zero -> skip 3 K-tiles
#define NKT1    48

// d_out layout: [output 65536][hs 2*BN*H][cs 2*BN*H][attw BN*S]
#define HS_OFF   65536
#define CS_OFF   (65536 + 2 * BN * H_)
#define ATT_OFF  (CS_OFF + 2 * BN * H_)

// ---------------- scratch (device globals; zero-initialized) ---------------
__device__ float g_feats [(size_t)BN * K0_LDA];   // fp32 (spmm gather chain)
__device__ float g_feats2[(size_t)BN * K1_LDA];
__device__ float g_energy[S_ * BN];
__device__ float g_dpw[S_ * BN];
__device__ int   g_csr_cnt[N_];
__device__ int   g_csr_col[(size_t)N_ * CSR_CAP];
__device__ float g_csr_val[(size_t)N_ * CSR_CAP];
// fp16 single-plane A operands, mma-fragment-linear (16x16 tiles, 512B, uint4/lane)
__device__ __half g_af0[(size_t)BN * K0_LDA];
__device__ __half g_af1[(size_t)BN * K1_LDA];
// fp16 single-plane weights, mma-fragment-linear
__device__ __half g_wt0[(size_t)512 * K0_LDA];
__device__ __half g_wt1[(size_t)512 * K1_LDA];
__device__ __half g_aw [(size_t)128 * 128];    // attn_w^T [n][k], fp16

__device__ __forceinline__ float sigmoidf_(float x) { return 1.f / (1.f + expf(-x)); }

__device__ __forceinline__ uint32_t smem_u32(const void* p) {
    uint32_t a;
    asm("{ .reg .u64 t; cvta.to.shared.u64 t, %1; cvt.u32.u64 %0, t; }"
        : "=r"(a) : "l"(p));
    return a;
}
__device__ __forceinline__ void ldsm_x4(uint32_t* r, uint32_t addr) {
    asm volatile("ldmatrix.sync.aligned.m8n8.x4.shared.b16 {%0,%1,%2,%3}, [%4];"
                 : "=r"(r[0]), "=r"(r[1]), "=r"(r[2]), "=r"(r[3]) : "r"(addr));
}
__device__ __forceinline__ void mma_f16(float* d, const uint32_t* a,
                                        const uint32_t* b) {
    asm volatile(
        "mma.sync.aligned.m16n8k16.row.col.f32.f16.f16.f32 "
        "{%0,%1,%2,%3}, {%4,%5,%6,%7}, {%8,%9}, {%0,%1,%2,%3};"
        : "+f"(d[0]), "+f"(d[1]), "+f"(d[2]), "+f"(d[3])
        : "r"(a[0]), "r"(a[1]), "r"(a[2]), "r"(a[3]), "r"(b[0]), "r"(b[1]));
}

// ---- A-fragment write: tile(rt,kt) 16x16 fp16, lane-major uint4 ----------
__device__ __forceinline__ void frag_write4(__half* __restrict__ p,
                                            size_t row, int col0, int nkt,
                                            float4 v) {
    int rt = (int)(row >> 4), r = (int)(row & 15);
    int kt = col0 >> 4, cc = col0 & 15;
    int lane0 = ((r & 7) << 2) | ((cc >> 1) & 3);
    int reg = (r >> 3) | ((cc >> 3) << 1);
    size_t base = ((size_t)rt * nkt + kt) * 256 + reg * 2;
    __half2 h01 = __floats2half2_rn(v.x, v.y);
    __half2 h23 = __floats2half2_rn(v.z, v.w);
    *(__half2*)(p + base + lane0 * 8) = h01;
    *(__half2*)(p + base + (lane0 + 1) * 8) = h23;
}
__device__ __forceinline__ void frag_write1(__half* __restrict__ p,
                                            size_t row, int col, int nkt, float v) {
    int rt = (int)(row >> 4), r = (int)(row & 15);
    int kt = col >> 4, cc = col & 15;
    size_t idx = ((size_t)rt * nkt + kt) * 256
               + (size_t)(((r & 7) << 2) | ((cc >> 1) & 3)) * 8
               + (size_t)((r >> 3) | ((cc >> 3) << 1)) * 2 + (cc & 1);
    p[idx] = __float2half_rn(v);
}
// ---- B-fragment addressing ------------------------------------------------
__device__ __forceinline__ size_t bfrag_idx(int k, int n, int nkt) {
    int nt2 = n >> 4, half = (n >> 3) & 1, kt = k >> 4, kk = k & 15;
    return ((size_t)nt2 * nkt + kt) * 256
         + (size_t)(((n & 7) << 2) | ((kk >> 1) & 3)) * 8
         + (size_t)((half << 1) | (kk >> 3)) * 2 + (kk & 1);
}

// ---------------- fused setup: csr + fills + weight splits -----------------
__global__ __launch_bounds__(256) void setup_kernel(
    const float* __restrict__ inputs, const float* __restrict__ h0,
    const float* __restrict__ h1, const float* __restrict__ sup,
    const float* __restrict__ w0, const float* __restrict__ w1,
    const float* __restrict__ aw) {
    int blk = blockIdx.x;
    int tid = threadIdx.x;
    if (blk < 128) {
        int n = blk * 8 + (tid >> 5);
        int lane = tid & 31;
        const float* row = sup + (size_t)n * N_;
        int cnt = 0;
        for (int base = 0; base < N_; base += 32) {
            float v = row[base + lane];
            unsigned mask = __ballot_sync(0xffffffffu, v != 0.f);
            if (v != 0.f) {
                int pos = cnt + __popc(mask & ((1u << lane) - 1u));
                if (pos < CSR_CAP) {
                    g_csr_col[n * CSR_CAP + pos] = base + lane;
                    g_csr_val[n * CSR_CAP + pos] = v;
                }
            }
            cnt += __popc(mask);
        }
        if (lane == 0) g_csr_cnt[n] = cnt < CSR_CAP ? cnt : CSR_CAP;
    } else if (blk < 8576) {
        int t = (blk - 128) * 256 + tid;
        if (t >= BN * 33) return;
        int r = t / 33, u = t - r * 33;
        float* dst = g_feats + (size_t)r * K0_LDA;
        if (u < 32) {
            float4 v = ((const float4*)(h0 + (size_t)r * H_))[u];
            ((float4*)dst)[u] = v;
            frag_write4(g_af0, (size_t)r, u * 4, NKT0, v);
        } else {
            float4 v = make_float4(inputs[r], 0.f, 0.f, 0.f);
            ((float4*)dst)[32] = v;
            frag_write4(g_af0, (size_t)r, 128, NKT0, v);
        }
    } else if (blk < 9472) {
        int t = (blk - 8576) * 256 + tid;
        if (t >= 512 * K0_LDA) return;
        int n_il = t / K0_LDA, k = t - n_il * K0_LDA;
        int n = (n_il & 3) * 128 + (n_il >> 2);
        int r = -1;
        if (k < 396) {
            int seg = (k * 0x3E1) >> 17;          // k/132 for k<396
            int p = k - seg * 132;
            int f = (p < 128) ? p + 1 : (p == 128 ? 0 : -1);
            if (f >= 0) r = seg * 129 + f;
        }
        float v = (r >= 0) ? w0[(size_t)r * NGATE + n] : 0.f;
        g_wt0[bfrag_idx(k, n_il, NKT0)] = __float2half_rn(v);
    } else if (blk < 11008) {
        int t = (blk - 9472) * 256 + tid;
        if (t >= 512 * K1_LDA) return;
        int n_il = t / K1_LDA, k = t - n_il * K1_LDA;
        int n = (n_il & 3) * 128 + (n_il >> 2);
        float v = w1[(size_t)k * NGATE + n];
        g_wt1[bfrag_idx(k, n_il, NKT1)] = __float2half_rn(v);
    } else if (blk < 11072) {
        int t = (blk - 11008) * 256 + tid;
        int n = t >> 7, k = t & 127;
        g_aw[t] = __float2half_rn(aw[k * 128 + n]);
    } else {
        int t = (blk - 11072) * 256 + tid;
        if (t >= BN * 32) return;
        int r = t >> 5, u = t & 31;
        float4 v = ((const float4*)(h1 + (size_t)r * H_))[u];
        ((float4*)(g_feats2 + (size_t)r * K1_LDA + 128))[u] = v;
        frag_write4(g_af1, (size_t)r, 128 + u * 4, NKT1, v);
    }
}

// ---------------- vectorized sparse diffusion + frag output ----------------
__global__ __launch_bounds__(128) void spmmv_kernel(int buf, int ld, int srcCol,
                                                    int dstCol, int prevCol,
                                                    int D4, int cheb,
                                                    int writeF32, int nkt) {
    __shared__ int   scol[CSR_CAP];   // pre-multiplied by ld
    __shared__ float sval[CSR_CAP];
    float* F = buf ? g_feats2 : g_feats;
    __half* AF = buf ? g_af1 : g_af0;
    int n = blockIdx.x;
    int tid = threadIdx.x, bq = tid >> 5, tq = tid & 31;
    int cnt = g_csr_cnt[n];
    for (int i = tid; i < cnt; i += 128) {
        scol[i] = g_csr_col[n * CSR_CAP + i] * ld;
        sval[i] = g_csr_val[n * CSR_CAP + i];
    }
    __syncthreads();
    int b = blockIdx.y * 4 + bq;
    size_t row = (size_t)b * N_ + n;
    const float* srcB = F + (size_t)b * N_ * ld + srcCol;
    size_t rbase = row * ld;
    for (int d0 = tq * 4; d0 < D4; d0 += 128) {
        float4 acc = make_float4(0.f, 0.f, 0.f, 0.f);
        for (int i = 0; i < cnt; i++) {
            const float4 v = *(const float4*)(srcB + scol[i] + d0);
            float s = sval[i];
            acc.x += s * v.x; acc.y += s * v.y; acc.z += s * v.z; acc.w += s * v.w;
        }
        if (cheb) {
            float4 p = *(const float4*)(F + rbase + prevCol + d0);
            acc.x = 2.f * acc.x - p.x; acc.y = 2.f * acc.y - p.y;
            acc.z = 2.f * acc.z - p.z; acc.w = 2.f * acc.w - p.w;
        }
        if (writeF32)
            *(float4*)(F + rbase + dstCol + d0) = acc;
        frag_write4(AF, row, dstCol + d0, nkt, acc);
    }
}

// ---------------- gates GEMM + fused LSTM: frag-A, triple-buffered ---------
// Block 64x128, 8 warps (2x4), warp tile 32x32, 2 CTA/SM.
// Per kt per warp: 2 LDG.128 A + 2 LDG.128 B (prefetch distance 2) + 8 HMMA.
// Compile-time trip counts -> full unroll, constant buffer rotation.
template <int NKTL, int NLOOP>
__global__ __launch_bounds__(256, 2) void gates_mma_kernel(
    const float* __restrict__ bias, const float* __restrict__ c_in,
    float* __restrict__ h_out, float* __restrict__ c_out, int layer) {
    const uint4* AF = layer ? (const uint4*)g_af1 : (const uint4*)g_af0;
    const uint4* BW = layer ? (const uint4*)g_wt1 : (const uint4*)g_wt0;

    int tid = threadIdx.x, lane = tid & 31, wid = tid >> 5;
    int warpM = wid & 1, warpN = wid >> 1;       // 2 x 4
    int colBase = blockIdx.x * 128;              // col fastest: A reuse in L2
    size_t rowBase = (size_t)blockIdx.y * 64;

    const size_t tstride = (size_t)NKTL * 32;    // uint4 per 16-row band
    size_t aOff0 = ((rowBase >> 4) + (size_t)warpM * 2) * tstride + lane;
    size_t aOff1 = aOff0 + tstride;
    size_t bOff0 = ((size_t)(colBase >> 4) + (size_t)warpN * 2) * tstride + lane;
    size_t bOff1 = bOff0 + tstride;

    float acc[2][2][2][4];
#pragma unroll
    for (int i = 0; i < 2; i++)
#pragma unroll
        for (int j = 0; j < 2; j++)
#pragma unroll
            for (int k = 0; k < 2; k++)
#pragma unroll
                for (int q = 0; q < 4; q++) acc[i][j][k][q] = 0.f;

    uint4 vA[3][2], vB[3][2];      // rotating triple buffer

#define GLOADBUF(bf, kt)                                                     \
    do {                                                                     \
        size_t ko = (size_t)(kt) * 32;                                       \
        vA[bf][0] = AF[aOff0 + ko];                                          \
        vA[bf][1] = AF[aOff1 + ko];                                          \
        vB[bf][0] = BW[bOff0 + ko];                                          \
        vB[bf][1] = BW[bOff1 + ko];                                          \
    } while (0)
#define GDOMMA(bf)                                                           \
    do {                                                                     \
        _Pragma("unroll")                                                    \
        for (int rt = 0; rt < 2; rt++) {                                     \
            const uint32_t* a = (const uint32_t*)&vA[bf][rt];                \
            _Pragma("unroll")                                                \
            for (int nt = 0; nt < 2; nt++) {                                 \
                const uint32_t* b = (const uint32_t*)&vB[bf][nt];            \
                mma_f16(acc[rt][nt][0], a, b);                               \
                mma_f16(acc[rt][nt][1], a, b + 2);                           \
            }                                                                \
        }                                                                    \
    } while (0)

    GLOADBUF(0, 0);
    GLOADBUF(1, 1);
#pragma unroll
    for (int kt = 0; kt < NLOOP; kt++) {
        if (kt + 2 < NLOOP) {
            switch ((kt + 2) % 3) {
                case 0: GLOADBUF(0, kt + 2); break;
                case 1: GLOADBUF(1, kt + 2); break;
                default: GLOADBUF(2, kt + 2); break;
            }
        }
        switch (kt % 3) {
            case 0: GDOMMA(0); break;
            case 1: GDOMMA(1); break;
            default: GDOMMA(2); break;
        }
    }
#undef GLOADBUF
#undef GDOMMA

    // ---- fused LSTM epilogue (col c = 4h+g; lane-pair shuffle) ----
    int evenp = (lane & 1) == 0;
#pragma unroll
    for (int rt = 0; rt < 2; rt++) {
#pragma unroll
        for (int rp = 0; rp < 2; rp++) {
            size_t row = rowBase + warpM * 32 + rt * 16 + rp * 8 + (lane >> 2);
#pragma unroll
            for (int nt = 0; nt < 2; nt++) {
#pragma unroll
                for (int hf = 0; hf < 2; hf++) {
                    int cbase = colBase + warpN * 32 + nt * 16 + hf * 8 + (lane & 3) * 2;
                    int h = cbase >> 2;
                    float a0 = acc[rt][nt][hf][rp * 2 + 0];
                    float a1 = acc[rt][nt][hf][rp * 2 + 1];
                    float v0, v1;
                    if (evenp) {
                        v0 = sigmoidf_(a0 + __ldg(bias + h));          // i
                        v1 = sigmoidf_(a1 + __ldg(bias + 128 + h));    // f
                    } else {
                        v0 = sigmoidf_(a0 + __ldg(bias + 256 + h));    // o
                        v1 = tanhf(a1 + __ldg(bias + 384 + h));        // g
                    }
                    float ex = __shfl_xor_sync(0xffffffffu, v1, 1);
                    float tn = 0.f;
                    if (evenp) {
                        float cin = c_in[row * H_ + h];
                        float cn = v1 * cin + v0 * ex;                 // f*c + i*g
                        c_out[row * H_ + h] = cn;
                        tn = tanhf(cn);
                    }
                    float t2 = __shfl_xor_sync(0xffffffffu, tn, 1);
                    if (!evenp) {
                        float hv = v0 * t2;                            // o*tanh(cn)
                        h_out[row * H_ + h] = hv;
                        if (layer == 0) {
                            g_feats2[row * (size_t)K1_LDA + h] = hv;
                            frag_write1(g_af1, row, h, NKT1, hv);
                        }
                    }
                }
            }
        }
    }
}

// ---------------- mma attention energy + dpw (fp16 2-product, smem) --------
#define SROW 12
#define STAGE_U32 (128 * SROW)
__global__ __launch_bounds__(256) void energy_mma_kernel(
    const float* __restrict__ enc, const float* __restrict__ attn_b,
    const float* __restrict__ proj_w, const float* __restrict__ hout) {
    __shared__ __align__(16) uint32_t sAh[2][STAGE_U32];
    __shared__ __align__(16) uint32_t sAl[2][STAGE_U32];
    __shared__ __align__(16) uint32_t sB [2][STAGE_U32];

    int tid = threadIdx.x, lane = tid & 31, wid = tid >> 5;
    int warpM = wid & 3, warpN = wid >> 2;
    size_t tileBase = (size_t)blockIdx.x * 128;

    uint32_t aAH[2], aAL[2], bAd[4];
#pragma unroll
    for (int am = 0; am < 2; am++) {
        int r = warpM * 32 + am * 16 + (lane & 15);
        int c = (lane >> 4) * 4;
        aAH[am] = smem_u32(&sAh[0][r * SROW + c]);
        aAL[am] = smem_u32(&sAl[0][r * SROW + c]);
    }
#pragma unroll
    for (int p = 0; p < 4; p++) {
        int quad = lane >> 3;
        int rowo = ((quad == 0 || quad == 1) ? 0 : 8) + (lane & 7);
        int c = (quad & 1) * 4;
        int n = warpN * 64 + p * 16 + rowo;
        bAd[p] = smem_u32(&sB[0][n * SROW + c]);
    }

    float acc[2][8][4];
#pragma unroll
    for (int i = 0; i < 2; i++)
#pragma unroll
        for (int j = 0; j < 8; j++)
#pragma unroll
            for (int q = 0; q < 4; q++) acc[i][j][q] = 0.f;

    int lr = tid >> 1;
    int lh = (tid & 1) * 8;
    const float* aSrc = enc + (tileBase + lr) * (size_t)H_ + lh;
    const uint4* bSrc = (const uint4*)(g_aw + (size_t)lr * 128 + lh);
    int dstIdx = lr * SROW + (lh >> 1);

    float dpw = 0.f;

    float4 pv0 = ((const float4*)aSrc)[0];
    float4 pv1 = ((const float4*)aSrc)[1];
    uint4 pb = bSrc[0];

    const int nch = H_ / 16;  // 8
    for (int kc = 0; kc < nch; kc++) {
        int st = kc & 1;
        {
            float vv[8] = {pv0.x, pv0.y, pv0.z, pv0.w, pv1.x, pv1.y, pv1.z, pv1.w};
            const float4* pwp = (const float4*)(proj_w + 128 + kc * 16 + lh);
            float4 w0 = __ldg(pwp), w1 = __ldg(pwp + 1);
            dpw += vv[0] * w0.x + vv[1] * w0.y + vv[2] * w0.z + vv[3] * w0.w
                 + vv[4] * w1.x + vv[5] * w1.y + vv[6] * w1.z + vv[7] * w1.w;
            uint32_t hh[4], ll[4];
#pragma unroll
            for (int i = 0; i < 4; i++) {
                float x = vv[2 * i], y = vv[2 * i + 1];
                __half2 hp = __floats2half2_rn(x, y);
                float2 hb = __half22float2(hp);
                __half2 lp = __floats2half2_rn(x - hb.x, y - hb.y);
                hh[i] = *(uint32_t*)&hp;
                ll[i] = *(uint32_t*)&lp;
            }
            *(uint4*)&sAh[st][dstIdx] = make_uint4(hh[0], hh[1], hh[2], hh[3]);
            *(uint4*)&sAl[st][dstIdx] = make_uint4(ll[0], ll[1], ll[2], ll[3]);
            *(uint4*)&sB [st][dstIdx] = pb;
        }
        __syncthreads();
        if (kc + 1 < nch) {
            const float4* s = (const float4*)(aSrc + (kc + 1) * 16);
            pv0 = s[0]; pv1 = s[1];
            pb = bSrc[(kc + 1) * 2];
        }
        uint32_t soff = st * (STAGE_U32 * 4);

        uint32_t aH[2][4], aL[2][4], bv[4][4];
#pragma unroll
        for (int am = 0; am < 2; am++) {
            ldsm_x4(aH[am], aAH[am] + soff);
            ldsm_x4(aL[am], aAL[am] + soff);
        }
#pragma unroll
        for (int p = 0; p < 4; p++)
            ldsm_x4(bv[p], bAd[p] + soff);

#pragma unroll
        for (int am = 0; am < 2; am++) {
#pragma unroll
            for (int p = 0; p < 4; p++) {
                mma_f16(acc[am][2 * p],     aH[am], &bv[p][0]);
                mma_f16(acc[am][2 * p],     aL[am], &bv[p][0]);
                mma_f16(acc[am][2 * p + 1], aH[am], &bv[p][2]);
                mma_f16(acc[am][2 * p + 1], aL[am], &bv[p][2]);
            }
        }
    }

    {
        float d2 = dpw + __shfl_xor_sync(0xffffffffu, dpw, 1);
        if ((tid & 1) == 0) g_dpw[tileBase + lr] = d2;
    }

    // epilogue: tanh(+b) * hout, reduce over 128 cols (scratch aliases sAh[0])
    float* sred = (float*)&sAh[0][0];
    float ev[2][2] = {{0.f, 0.f}, {0.f, 0.f}};
#pragma unroll
    for (int am = 0; am < 2; am++) {
        size_t gr0 = tileBase + warpM * 32 + am * 16 + (lane >> 2);
        size_t gr1 = gr0 + 8;
        const float* h0p = hout + (size_t)(gr0 & (BN - 1)) * H_;
        const float* h1p = hout + (size_t)(gr1 & (BN - 1)) * H_;
#pragma unroll
        for (int bn = 0; bn < 8; bn++) {
            int col = warpN * 64 + bn * 8 + (lane & 3) * 2;
            float2 bb = *(const float2*)(attn_b + col);
            float2 h0 = *(const float2*)(h0p + col);
            float2 h1 = *(const float2*)(h1p + col);
            ev[am][0] += tanhf(acc[am][bn][0] + bb.x) * h0.x
                       + tanhf(acc[am][bn][1] + bb.y) * h0.y;
            ev[am][1] += tanhf(acc[am][bn][2] + bb.x) * h1.x
                       + tanhf(acc[am][bn][3] + bb.y) * h1.y;
        }
    }
#pragma unroll
    for (int am = 0; am < 2; am++)
#pragma unroll
        for (int rp = 0; rp < 2; rp++) {
            ev[am][rp] += __shfl_xor_sync(0xffffffffu, ev[am][rp], 1);
            ev[am][rp] += __shfl_xor_sync(0xffffffffu, ev[am][rp], 2);
        }
    if (warpN == 1 && (lane & 3) == 0) {
#pragma unroll
        for (int am = 0; am < 2; am++)
#pragma unroll
            for (int rp = 0; rp < 2; rp++)
                sred[((warpM * 2 + am) * 2 + rp) * 8 + (lane >> 2)] = ev[am][rp];
    }
    __syncthreads();
    if (warpN == 0 && (lane & 3) == 0) {
#pragma unroll
        for (int am = 0; am < 2; am++)
#pragma unroll
            for (int rp = 0; rp < 2; rp++) {
                size_t gr = tileBase + warpM * 32 + am * 16 + rp * 8 + (lane >> 2);
                g_energy[gr] = ev[am][rp]
                    + sred[((warpM * 2 + am) * 2 + rp) * 8 + (lane >> 2)];
            }
    }
}

// ---------------- softmax over S + attw + final projection -----------------
__global__ void softmax_out_kernel(const float* __restrict__ proj_w,
                                   const float* __restrict__ proj_b,
                                   const float* __restrict__ hout,
                                   float* __restrict__ out0,
                                   float* __restrict__ attw) {
    int gwarp = (blockIdx.x * blockDim.x + threadIdx.x) >> 5;
    int lane = threadIdx.x & 31;
    if (gwarp >= BN) return;
    int bn = gwarp;

    float e = (lane < S_) ? g_energy[lane * BN + bn] : -1e30f;
    float m = e;
#pragma unroll
    for (int off = 16; off > 0; off >>= 1)
        m = fmaxf(m, __shfl_xor_sync(0xffffffffu, m, off));
    float p = (lane < S_) ? expf(e - m) : 0.f;
    float s = p;
#pragma unroll
    for (int off = 16; off > 0; off >>= 1)
        s += __shfl_xor_sync(0xffffffffu, s, off);
    float a = p / s;
    if (lane < S_) attw[(size_t)bn * S_ + lane] = a;

    float acc = (lane < S_) ? a * g_dpw[lane * BN + bn] : 0.f;
#pragma unroll
    for (int j = 0; j < 4; j++) {
        int col = lane + j * 32;
        acc += hout[(size_t)bn * H_ + col] * proj_w[col];
    }
#pragma unroll
    for (int off = 16; off > 0; off >>= 1)
        acc += __shfl_xor_sync(0xffffffffu, acc, off);
    if (lane == 0) out0[bn] = acc + proj_b[0];
}

// ---------------- orchestration: kernel launches ONLY ----------------------
extern "C" void kernel_launch(void* const* d_in, const int* in_sizes, int n_in,
                              void* d_out, int out_size) {
    const float* inputs  = (const float*)d_in[0];
    const float* enc     = (const float*)d_in[1];
    const float* hidden  = (const float*)d_in[2];
    const float* cell    = (const float*)d_in[3];
    const float* sup     = (const float*)d_in[4];
    const float* w0      = (const float*)d_in[5];
    const float* b0      = (const float*)d_in[6];
    const float* w1      = (const float*)d_in[7];
    const float* b1      = (const float*)d_in[8];
    const float* attn_w  = (const float*)d_in[9];
    const float* attn_b  = (const float*)d_in[10];
    const float* proj_w  = (const float*)d_in[11];
    const float* proj_b  = (const float*)d_in[12];
    float* out = (float*)d_out;

    float* hs0 = out + HS_OFF;
    float* hs1 = out + HS_OFF + (size_t)BN * H_;
    float* cs0 = out + CS_OFF;
    float* cs1 = out + CS_OFF + (size_t)BN * H_;
    float* attw = out + ATT_OFF;

    // launch index 3 = gates_mma layer0 (ncu samples index 3)
    setup_kernel<<<19264, 256>>>(inputs, hidden, hidden + (size_t)BN * H_,
                                 sup, w0, w1, attn_w);                             // 0
    spmmv_kernel<<<dim3(N_, B_ / 4), 128>>>(0, K0_LDA, 0, 132, -1, 132, 0, 1, NKT0);   // 1
    spmmv_kernel<<<dim3(N_, B_ / 4), 128>>>(0, K0_LDA, 132, 264, 0, 132, 1, 0, NKT0);  // 2
    gates_mma_kernel<NKT0, NKT0_LOOP><<<dim3(4, BN / 64), 256>>>(
        b0, cell, hs0, cs0, 0);                                                    // 3
    spmmv_kernel<<<dim3(N_, B_ / 4), 128>>>(1, K1_LDA, 0, 256, -1, 256, 0, 1, NKT1);   // 4
    spmmv_kernel<<<dim3(N_, B_ / 4), 128>>>(1, K1_LDA, 256, 512, 0, 256, 1, 0, NKT1);  // 5
    gates_mma_kernel<NKT1, NKT1><<<dim3(4, BN / 64), 256>>>(
        b1, cell + (size_t)BN * H_, hs1, cs1, 1);                                  // 6
    energy_mma_kernel<<<(S_ * BN) / 128, 256>>>(enc, attn_b, proj_w, hs1);         // 7
    softmax_out_kernel<<<BN / 8, 256>>>(proj_w, proj_b, hs1, out, attw);           // 8
}